// round 5
// baseline (speedup 1.0000x reference)
#include <cuda_runtime.h>
#include <cuda_bf16.h>
#include <math.h>
#include <stdint.h>

// Problem constants
#define NB   8192          // batch
#define NV   778           // vertices
#define KC   512           // padded K (3x160 split: [Xhi|Xlo|Xhi] vs [Chi|Chi|Clo])
#define NP   1024          // padded N
#define BKC  32            // k per pipeline chunk
#define NCH  16            // 512 / 32

// ---------------- scratch (device globals; zero-initialized at load) ----------------
__device__ __nv_bfloat16 g_Xh[(size_t)NB * KC];   // [b][k]  A operand bf16
__device__ __nv_bfloat16 g_Cb[(size_t)KC * NP];   // [k][o]  B operand bf16
__device__ float  g_A[NB * 192];                  // [b][j][3x4]
__device__ float  g_Mt[(size_t)NP * NB];          // GEMM output, TRANSPOSED [o][b]
__device__ float  g_Js[480];
__device__ float  g_J0[48];
__device__ float  g_W[336];

// ---------------- helpers ----------------
__device__ __forceinline__ void write_hl(__nv_bfloat16* base, int s, float v) {
    __nv_bfloat16 h = __float2bfloat16(v);
    __nv_bfloat16 l = __float2bfloat16(v - __bfloat162float(h));
    base[s] = h; base[160 + s] = l; base[320 + s] = h;
}
__device__ __forceinline__ void ldsm_x4(uint32_t* r, uint32_t addr) {
    asm volatile("ldmatrix.sync.aligned.m8n8.x4.shared.b16 {%0,%1,%2,%3}, [%4];"
                 : "=r"(r[0]), "=r"(r[1]), "=r"(r[2]), "=r"(r[3]) : "r"(addr));
}
__device__ __forceinline__ void ldsm_x2_t(uint32_t* r, uint32_t addr) {
    asm volatile("ldmatrix.sync.aligned.m8n8.x2.trans.shared.b16 {%0,%1}, [%2];"
                 : "=r"(r[0]), "=r"(r[1]) : "r"(addr));
}
__device__ __forceinline__ void mma16816(float* d, const uint32_t* a, const uint32_t* b) {
    asm volatile("mma.sync.aligned.m16n8k16.row.col.f32.bf16.bf16.f32 "
                 "{%0,%1,%2,%3}, {%4,%5,%6,%7}, {%8,%9}, {%0,%1,%2,%3};"
                 : "+f"(d[0]), "+f"(d[1]), "+f"(d[2]), "+f"(d[3])
                 : "r"(a[0]), "r"(a[1]), "r"(a[2]), "r"(a[3]), "r"(b[0]), "r"(b[1]));
}
__device__ __forceinline__ void cp16(uint32_t saddr, const void* g) {
    asm volatile("cp.async.cg.shared.global [%0], [%1], 16;" :: "r"(saddr), "l"(g) : "memory");
}
#define CP_COMMIT() asm volatile("cp.async.commit_group;" ::: "memory")
#define CP_WAIT1()  asm volatile("cp.async.wait_group 1;" ::: "memory")
#define CP_WAIT0()  asm volatile("cp.async.wait_group 0;" ::: "memory")
// A staging: 64B rows (32 halfs), swizzle bits[5:4] ^= bits[7:6]
#define SWA(o) ((o) ^ (((o) >> 2) & 0x30))
// B staging: 256B rows (128 halfs), swizzle bits[6:4] ^= bits[10:8]
#define SWB(o) ((o) ^ (((o) >> 4) & 0x70))

// =====================================================================
// Kernel 1: precomp_all — blocks 0..145: C factor (hi/lo bf16, [k][o] layout);
//           blocks 146..172: small reductions (Js, J0, W).
// =====================================================================
__global__ __launch_bounds__(1024) void precomp_all(
    const float* __restrict__ vt, const float* __restrict__ sd,
    const float* __restrict__ pd, const float* __restrict__ Jr,
    const float* __restrict__ wts)
{
    __shared__ float sB[64 * 3];
    __shared__ float sW[64 * 16];
    __shared__ float sJr[64 * 21];
    __shared__ float part[2][1008];

    int t = threadIdx.x;
    int bid = blockIdx.x;

    if (bid < 146) {
        int f = bid;
        const float* brow = (f == 0) ? vt : ((f <= 10) ? (sd + (f - 1) * 2334)
                                                       : (pd + (f - 11) * 2334));
        int vg = t / 336;        // 0..2 (t < 1008)
        int o  = t % 336;
        int j = o / 21, k = o % 21;
        bool act = (t < 1008);
        float a0 = 0.f, a1 = 0.f, a2 = 0.f;

        for (int v0 = 0; v0 < NV; v0 += 64) {
            int nv = min(64, NV - v0);
            for (int i = t; i < nv * 3;  i += 1024) sB[i]  = brow[v0 * 3 + i];
            for (int i = t; i < nv * 16; i += 1024) sW[i]  = wts[v0 * 16 + i];
            for (int i = t; i < nv * 21; i += 1024) sJr[i] = Jr[v0 * 21 + i];
            __syncthreads();
            if (act) {
                for (int v = vg; v < nv; v += 3) {
                    float p = sW[v * 16 + j] * sJr[v * 21 + k];
                    a0 = fmaf(p, sB[v * 3 + 0], a0);
                    a1 = fmaf(p, sB[v * 3 + 1], a1);
                    a2 = fmaf(p, sB[v * 3 + 2], a2);
                }
            }
            __syncthreads();
        }
        if (act && vg > 0) {
            part[vg - 1][o * 3 + 0] = a0;
            part[vg - 1][o * 3 + 1] = a1;
            part[vg - 1][o * 3 + 2] = a2;
        }
        __syncthreads();
        if (t < 336) {
            float v[3];
            v[0] = a0 + part[0][t * 3 + 0] + part[1][t * 3 + 0];
            v[1] = a1 + part[0][t * 3 + 1] + part[1][t * 3 + 1];
            v[2] = a2 + part[0][t * 3 + 2] + part[1][t * 3 + 2];
            #pragma unroll
            for (int c = 0; c < 3; c++) {
                __nv_bfloat16 ch = __float2bfloat16(v[c]);
                __nv_bfloat16 cl = __float2bfloat16(v[c] - __bfloat162float(ch));
                int ol = t * 3 + c;       // (j*21+k)*3+c
                g_Cb[(size_t)f * NP + ol]         = ch;
                g_Cb[(size_t)(160 + f) * NP + ol] = ch;
                g_Cb[(size_t)(320 + f) * NP + ol] = cl;
            }
        }
    } else {
        int gw   = (bid - 146) * 32 + (t >> 5);    // 0..863
        int lane = t & 31;
        float acc = 0.f;
        if (gw < 480) {                 // Js[s][j][c]
            int s = gw / 48, r = gw % 48, j = r / 3, c = r % 3;
            for (int v = lane; v < NV; v += 32)
                acc = fmaf(Jr[v * 21 + j], sd[s * 2334 + v * 3 + c], acc);
        } else if (gw < 528) {          // J0[j][c]
            int idx = gw - 480, j = idx / 3, c = idx % 3;
            for (int v = lane; v < NV; v += 32)
                acc = fmaf(Jr[v * 21 + j], vt[v * 3 + c], acc);
        } else {                        // W[k][j]
            int idx = gw - 528, k = idx / 16, j = idx % 16;
            for (int v = lane; v < NV; v += 32)
                acc = fmaf(Jr[v * 21 + k], wts[v * 16 + j], acc);
        }
        #pragma unroll
        for (int off = 16; off > 0; off >>= 1)
            acc += __shfl_down_sync(0xffffffffu, acc, off);
        if (lane == 0) {
            if (gw < 480)      g_Js[gw] = acc;
            else if (gw < 528) g_J0[gw - 480] = acc;
            else               g_W[gw - 528] = acc;
        }
    }
}

// =====================================================================
// Kernel 2: per-batch forward kinematics. One warp per batch.
// Produces g_Xh[b][512] (hi/lo bf16) and g_A[b][16][12].
// =====================================================================
__global__ __launch_bounds__(256) void fk_kernel(
    const float* __restrict__ beta, const float* __restrict__ theta,
    const float* __restrict__ wrist, const float* __restrict__ hc,
    const float* __restrict__ hm)
{
    __shared__ float sE[8][48];
    __shared__ float sR[8][16][9];
    __shared__ float sJ[8][16][3];
    __shared__ float sG[8][16][12];

    int w = threadIdx.x >> 5, lane = threadIdx.x & 31;
    int b = blockIdx.x * 8 + w;
    __nv_bfloat16* xrow = g_Xh + (size_t)b * KC;

    for (int e = lane; e < 45; e += 32) {
        float v = hm[e];
        #pragma unroll
        for (int s = 0; s < 10; s++)
            v = fmaf(theta[b * 10 + s], hc[s * 45 + e], v);
        sE[w][e] = v;
    }
    __syncwarp();

    if (lane < 16) {
        float r0, r1, r2;
        if (lane == 0) { r0 = wrist[b * 3]; r1 = wrist[b * 3 + 1]; r2 = wrist[b * 3 + 2]; }
        else { int e = (lane - 1) * 3; r0 = sE[w][e]; r1 = sE[w][e + 1]; r2 = sE[w][e + 2]; }
        float t0 = r0 + 1e-8f, t1 = r1 + 1e-8f, t2 = r2 + 1e-8f;
        float ang = sqrtf(t0 * t0 + t1 * t1 + t2 * t2);
        float inv = 1.0f / ang;
        float x = r0 * inv, y = r1 * inv, z = r2 * inv;
        float s, c;
        sincosf(ang, &s, &c);
        float ic = 1.0f - c;
        float R[9];
        R[0] = 1.0f - ic * (y * y + z * z);
        R[1] = -s * z + ic * x * y;
        R[2] =  s * y + ic * x * z;
        R[3] =  s * z + ic * x * y;
        R[4] = 1.0f - ic * (x * x + z * z);
        R[5] = -s * x + ic * y * z;
        R[6] = -s * y + ic * x * z;
        R[7] =  s * x + ic * y * z;
        R[8] = 1.0f - ic * (x * x + y * y);
        #pragma unroll
        for (int m = 0; m < 9; m++) sR[w][lane][m] = R[m];
        if (lane >= 1) {
            int s0 = 11 + (lane - 1) * 9;
            #pragma unroll
            for (int m = 0; m < 9; m++)
                write_hl(xrow, s0 + m, R[m] - ((m == 0 || m == 4 || m == 8) ? 1.0f : 0.0f));
        }
    }
    if (lane == 0)  write_hl(xrow, 0, 1.0f);
    if (lane < 10)  write_hl(xrow, 1 + lane, beta[b * 10 + lane]);

    if (lane < 16) {
        float jx = g_J0[lane * 3 + 0], jy = g_J0[lane * 3 + 1], jz = g_J0[lane * 3 + 2];
        #pragma unroll
        for (int s = 0; s < 10; s++) {
            float bs = beta[b * 10 + s];
            jx = fmaf(bs, g_Js[s * 48 + lane * 3 + 0], jx);
            jy = fmaf(bs, g_Js[s * 48 + lane * 3 + 1], jy);
            jz = fmaf(bs, g_Js[s * 48 + lane * 3 + 2], jz);
        }
        sJ[w][lane][0] = jx; sJ[w][lane][1] = jy; sJ[w][lane][2] = jz;
    }
    __syncwarp();

    if (lane == 0) {
        #pragma unroll
        for (int c = 0; c < 3; c++) {
            #pragma unroll
            for (int d = 0; d < 3; d++) sG[w][0][c * 4 + d] = sR[w][0][c * 3 + d];
            sG[w][0][c * 4 + 3] = sJ[w][0][c];
        }
    }
    __syncwarp();

    if (lane < 5) {
        float pr[9], pt[3];
        #pragma unroll
        for (int c = 0; c < 3; c++) {
            #pragma unroll
            for (int d = 0; d < 3; d++) pr[c * 3 + d] = sG[w][0][c * 4 + d];
            pt[c] = sG[w][0][c * 4 + 3];
        }
        int p = 0;
        #pragma unroll
        for (int st = 0; st < 3; st++) {
            int j = 1 + lane * 3 + st;
            float rj[9];
            #pragma unroll
            for (int m = 0; m < 9; m++) rj[m] = sR[w][j][m];
            float nr[9], nt[3];
            #pragma unroll
            for (int c = 0; c < 3; c++)
                #pragma unroll
                for (int d = 0; d < 3; d++)
                    nr[c * 3 + d] = pr[c * 3 + 0] * rj[0 * 3 + d]
                                  + pr[c * 3 + 1] * rj[1 * 3 + d]
                                  + pr[c * 3 + 2] * rj[2 * 3 + d];
            float dx = sJ[w][j][0] - sJ[w][p][0];
            float dy = sJ[w][j][1] - sJ[w][p][1];
            float dz = sJ[w][j][2] - sJ[w][p][2];
            #pragma unroll
            for (int c = 0; c < 3; c++)
                nt[c] = pr[c * 3 + 0] * dx + pr[c * 3 + 1] * dy + pr[c * 3 + 2] * dz + pt[c];
            #pragma unroll
            for (int c = 0; c < 3; c++) {
                #pragma unroll
                for (int d = 0; d < 3; d++) sG[w][j][c * 4 + d] = nr[c * 3 + d];
                sG[w][j][c * 4 + 3] = nt[c];
            }
            #pragma unroll
            for (int m = 0; m < 9; m++) pr[m] = nr[m];
            pt[0] = nt[0]; pt[1] = nt[1]; pt[2] = nt[2];
            p = j;
        }
    }
    __syncwarp();

    if (lane < 16) {
        float jx = sJ[w][lane][0], jy = sJ[w][lane][1], jz = sJ[w][lane][2];
        #pragma unroll
        for (int c = 0; c < 3; c++) {
            float a0 = sG[w][lane][c * 4 + 0];
            float a1 = sG[w][lane][c * 4 + 1];
            float a2 = sG[w][lane][c * 4 + 2];
            float at = sG[w][lane][c * 4 + 3] - (a0 * jx + a1 * jy + a2 * jz);
            int base = b * 192 + lane * 12 + c * 4;
            g_A[base + 0] = a0; g_A[base + 1] = a1;
            g_A[base + 2] = a2; g_A[base + 3] = at;
        }
    }
}

// =====================================================================
// Kernel 3: bf16 mma.sync GEMM, output transposed: Mt[o][b].
// CTA tile 128x128, BK=32, 3-stage cp.async pipeline, warp tile 64x32.
// Epilogue transposes acc via smem (union with dead pipeline buffers).
// =====================================================================
union SmemU {
    struct {
        __nv_bfloat16 A[3][128 * BKC];   // [st][m][k] 64B rows
        __nv_bfloat16 B[3][BKC * 128];   // [st][k][n] 256B rows
    } p;
    float T[128][65];                    // epilogue transpose buffer
};

__global__ __launch_bounds__(256) void mma_kernel()
{
    __shared__ __align__(128) SmemU smu;

    const int tid = threadIdx.x;
    const int wid = tid >> 5, lane = tid & 31;
    const int bn0 = blockIdx.x * 128;
    const int bm0 = blockIdx.y * 128;
    const int warp_m = (wid & 1) * 64;
    const int warp_n = (wid >> 1) * 32;

    const uint32_t smA_u = (uint32_t)__cvta_generic_to_shared(&smu.p.A[0][0]);
    const uint32_t smB_u = (uint32_t)__cvta_generic_to_shared(&smu.p.B[0][0]);

    float acc[4][4][4];
    #pragma unroll
    for (int mt = 0; mt < 4; mt++)
        #pragma unroll
        for (int nt = 0; nt < 4; nt++)
            #pragma unroll
            for (int q = 0; q < 4; q++) acc[mt][nt][q] = 0.f;

    auto load_chunk = [&](int kc, int st) {
        #pragma unroll
        for (int i = 0; i < 2; i++) {
            int idx = i * 256 + tid;
            int row = idx >> 2, c16 = idx & 3;
            uint32_t off = SWA((uint32_t)(row * 64 + c16 * 16));
            cp16(smA_u + st * 8192 + off,
                 g_Xh + (size_t)(bm0 + row) * KC + kc * BKC + c16 * 8);
        }
        #pragma unroll
        for (int i = 0; i < 2; i++) {
            int idx = i * 256 + tid;
            int row = idx >> 4, c16 = idx & 15;
            uint32_t off = SWB((uint32_t)(row * 256 + c16 * 16));
            cp16(smB_u + st * 8192 + off,
                 g_Cb + (size_t)(kc * BKC + row) * NP + bn0 + c16 * 8);
        }
    };

    load_chunk(0, 0); CP_COMMIT();
    load_chunk(1, 1); CP_COMMIT();

    const int r15 = lane & 15;
    const int kq  = lane >> 4;

    #pragma unroll 1
    for (int kc = 0; kc < NCH; kc++) {
        CP_WAIT1();
        __syncthreads();
        int nk = kc + 2;
        if (nk < NCH) load_chunk(nk, nk % 3);
        CP_COMMIT();

        int st = kc % 3;
        #pragma unroll
        for (int ks = 0; ks < 2; ks++) {
            uint32_t a[4][4], b[4][2];
            #pragma unroll
            for (int mt = 0; mt < 4; mt++) {
                uint32_t off = (uint32_t)((warp_m + mt * 16 + r15) * 64
                                          + (ks * 16 + kq * 8) * 2);
                ldsm_x4(a[mt], smA_u + st * 8192 + SWA(off));
            }
            #pragma unroll
            for (int nt = 0; nt < 4; nt++) {
                uint32_t off = (uint32_t)((ks * 16 + r15) * 256
                                          + (warp_n + nt * 8) * 2);
                ldsm_x2_t(b[nt], smB_u + st * 8192 + SWB(off));
            }
            #pragma unroll
            for (int mt = 0; mt < 4; mt++)
                #pragma unroll
                for (int nt = 0; nt < 4; nt++)
                    mma16816(acc[mt][nt], a[mt], b[nt]);
        }
    }

    // ---- epilogue: transpose via smem, write Mt[o][b] coalesced ----
    CP_WAIT0();
    __syncthreads();          // pipeline buffers now dead; union T is free

    #pragma unroll
    for (int h = 0; h < 2; h++) {
        if (((wid >> 1) >> 1) == h) {       // warps owning cols [h*64, h*64+64)
            #pragma unroll
            for (int mt = 0; mt < 4; mt++) {
                #pragma unroll
                for (int nt = 0; nt < 4; nt++) {
                    int cl = warp_n - h * 64 + nt * 8 + (lane & 3) * 2;
                    int r  = warp_m + mt * 16 + (lane >> 2);
                    smu.T[r][cl]         = acc[mt][nt][0];
                    smu.T[r][cl + 1]     = acc[mt][nt][1];
                    smu.T[r + 8][cl]     = acc[mt][nt][2];
                    smu.T[r + 8][cl + 1] = acc[mt][nt][3];
                }
            }
        }
        __syncthreads();
        {
            int ol = tid >> 2, seg = tid & 3;
            size_t obase = (size_t)(bn0 + h * 64 + ol) * NB + bm0 + seg * 32;
            #pragma unroll
            for (int g = 0; g < 8; g++) {
                float4 v = make_float4(smu.T[seg * 32 + g * 4 + 0][ol],
                                       smu.T[seg * 32 + g * 4 + 1][ol],
                                       smu.T[seg * 32 + g * 4 + 2][ol],
                                       smu.T[seg * 32 + g * 4 + 3][ol]);
                *(float4*)&g_Mt[obase + g * 4] = v;
            }
        }
        __syncthreads();
    }
}

// =====================================================================
// Kernel 4: joints[b,k,c] = sum_j ( A[b,j,c,:3].Mt[:, b] + A[b,j,c,3]*W[k,j] )
// 256 CTAs x 256 thr: 32 batches x 8 j-groups (2 j each), jacc[63] in regs.
// Mt reads: o = j*63 + k*3 + d, lane -> b (coalesced 128B).
// =====================================================================
__global__ __launch_bounds__(256) void reduce_kernel(float* __restrict__ out)
{
    __shared__ float sAff[32][192];
    __shared__ float sWt[336];
    __shared__ float jp[32][64];

    int tid = threadIdx.x;
    int jg = tid >> 5, bl = tid & 31;
    int b0 = blockIdx.x * 32;

    for (int i = tid; i < 336; i += 256) sWt[i] = g_W[i];
    for (int i = tid; i < 1536; i += 256)
        ((float4*)&sAff[0][0])[i] = ((const float4*)&g_A[b0 * 192])[i];
    __syncthreads();

    float jacc[63];
    #pragma unroll
    for (int i = 0; i < 63; i++) jacc[i] = 0.f;

    #pragma unroll
    for (int jj = 0; jj < 2; jj++) {
        int j = jg * 2 + jj;
        float A12[12];
        #pragma unroll
        for (int q = 0; q < 3; q++)
            *(float4*)&A12[q * 4] = *(float4*)&sAff[bl][j * 12 + q * 4];
        const float* mt = g_Mt + (size_t)(j * 63) * NB + b0 + bl;
        #pragma unroll
        for (int k = 0; k < 21; k++) {
            #pragma unroll
            for (int d = 0; d < 3; d++) {
                float val = mt[(size_t)(k * 3 + d) * NB];
                jacc[k * 3 + 0] = fmaf(A12[0 + d], val, jacc[k * 3 + 0]);
                jacc[k * 3 + 1] = fmaf(A12[4 + d], val, jacc[k * 3 + 1]);
                jacc[k * 3 + 2] = fmaf(A12[8 + d], val, jacc[k * 3 + 2]);
            }
            float wv = sWt[k * 16 + j];
            jacc[k * 3 + 0] = fmaf(A12[3],  wv, jacc[k * 3 + 0]);
            jacc[k * 3 + 1] = fmaf(A12[7],  wv, jacc[k * 3 + 1]);
            jacc[k * 3 + 2] = fmaf(A12[11], wv, jacc[k * 3 + 2]);
        }
    }

    // combine 8 j-groups (deterministic pass order)
    #pragma unroll 1
    for (int p = 0; p < 8; p++) {
        if (jg == p) {
            if (p == 0) {
                #pragma unroll
                for (int i = 0; i < 63; i++) jp[bl][i] = jacc[i];
            } else {
                #pragma unroll
                for (int i = 0; i < 63; i++) jp[bl][i] += jacc[i];
            }
        }
        __syncthreads();
    }

    for (int i = tid; i < 32 * 63; i += 256)
        out[b0 * 63 + i] = jp[i / 63][i % 63];
}

// =====================================================================
extern "C" void kernel_launch(void* const* d_in, const int* in_sizes, int n_in,
                              void* d_out, int out_size)
{
    const float* beta  = (const float*)d_in[0];
    const float* theta = (const float*)d_in[1];
    const float* wrist = (const float*)d_in[2];
    const float* vt    = (const float*)d_in[3];
    const float* sd    = (const float*)d_in[4];
    const float* pd    = (const float*)d_in[5];
    const float* Jr    = (const float*)d_in[6];
    const float* hc    = (const float*)d_in[7];
    const float* hm    = (const float*)d_in[8];
    const float* wts   = (const float*)d_in[9];
    float* out = (float*)d_out;

    precomp_all<<<173, 1024>>>(vt, sd, pd, Jr, wts);
    fk_kernel<<<1024, 256>>>(beta, theta, wrist, hc, hm);
    mma_kernel<<<dim3(NP / 128, NB / 128), 256>>>();
    reduce_kernel<<<256, 256>>>(out);
}

// round 6
// speedup vs baseline: 1.8021x; 1.8021x over previous
#include <cuda_runtime.h>
#include <cuda_bf16.h>
#include <math.h>
#include <stdint.h>

// Problem constants
#define NB   8192          // batch
#define NV   778           // vertices
#define KC   512           // padded K stride (3x160 split: [Xhi|Xlo|Xhi] vs [Chi|Chi|Clo])
#define NP   1024          // padded N
#define BKC  32            // k per pipeline chunk
#define NCH  15            // 480 / 32 used chunks
#define NVS  4             // vertex splits for precomp_C
#define VPB  195           // verts per split block

// ---------------- scratch (device globals; zero-initialized at load) ----------------
__device__ __nv_bfloat16 g_Xh[(size_t)NB * KC];   // [b][k]  A operand bf16
__device__ __nv_bfloat16 g_Cb[(size_t)KC * NP];   // [k][o]  B operand bf16
__device__ float  g_Cp[NVS * 146 * 1008];         // fp32 partials of C
__device__ float  g_A[NB * 192];                  // [b][j][3x4]
__device__ float  g_M[(size_t)NB * NP];           // GEMM output [b][o]
__device__ float  g_Js[480];
__device__ float  g_J0[48];
__device__ float  g_W[336];

// ---------------- helpers ----------------
__device__ __forceinline__ void write_hl(__nv_bfloat16* base, int s, float v) {
    __nv_bfloat16 h = __float2bfloat16(v);
    __nv_bfloat16 l = __float2bfloat16(v - __bfloat162float(h));
    base[s] = h; base[160 + s] = l; base[320 + s] = h;
}
__device__ __forceinline__ void ldsm_x4(uint32_t* r, uint32_t addr) {
    asm volatile("ldmatrix.sync.aligned.m8n8.x4.shared.b16 {%0,%1,%2,%3}, [%4];"
                 : "=r"(r[0]), "=r"(r[1]), "=r"(r[2]), "=r"(r[3]) : "r"(addr));
}
__device__ __forceinline__ void ldsm_x2_t(uint32_t* r, uint32_t addr) {
    asm volatile("ldmatrix.sync.aligned.m8n8.x2.trans.shared.b16 {%0,%1}, [%2];"
                 : "=r"(r[0]), "=r"(r[1]) : "r"(addr));
}
__device__ __forceinline__ void mma16816(float* d, const uint32_t* a, const uint32_t* b) {
    asm volatile("mma.sync.aligned.m16n8k16.row.col.f32.bf16.bf16.f32 "
                 "{%0,%1,%2,%3}, {%4,%5,%6,%7}, {%8,%9}, {%0,%1,%2,%3};"
                 : "+f"(d[0]), "+f"(d[1]), "+f"(d[2]), "+f"(d[3])
                 : "r"(a[0]), "r"(a[1]), "r"(a[2]), "r"(a[3]), "r"(b[0]), "r"(b[1]));
}
__device__ __forceinline__ void cp16(uint32_t saddr, const void* g) {
    asm volatile("cp.async.cg.shared.global [%0], [%1], 16;" :: "r"(saddr), "l"(g) : "memory");
}
#define CP_COMMIT() asm volatile("cp.async.commit_group;" ::: "memory")
#define CP_WAIT1()  asm volatile("cp.async.wait_group 1;" ::: "memory")
// A staging: 64B rows (32 halfs), swizzle bits[5:4] ^= bits[7:6]
#define SWA(o) ((o) ^ (((o) >> 2) & 0x30))
// B staging: 256B rows (128 halfs), swizzle bits[6:4] ^= bits[10:8]
#define SWB(o) ((o) ^ (((o) >> 4) & 0x70))

// =====================================================================
// Kernel 1: precomp_part — blocks 0..583: C partials over vertex splits;
//           blocks 584..655: small reductions (Js, J0, W).
// =====================================================================
__global__ __launch_bounds__(384) void precomp_part(
    const float* __restrict__ vt, const float* __restrict__ sd,
    const float* __restrict__ pd, const float* __restrict__ Jr,
    const float* __restrict__ wts)
{
    __shared__ float sB[64 * 3];
    __shared__ float sW[64 * 16];
    __shared__ float sJr[64 * 21];

    int t = threadIdx.x;
    int bid = blockIdx.x;

    if (bid < 146 * NVS) {
        int f  = bid >> 2;
        int vs = bid & 3;
        const float* brow = (f == 0) ? vt : ((f <= 10) ? (sd + (f - 1) * 2334)
                                                       : (pd + (f - 11) * 2334));
        int vstart = vs * VPB;
        int vend   = min(NV, vstart + VPB);
        int j = t / 21, k = t % 21;
        bool active = (t < 336);
        float a0 = 0.f, a1 = 0.f, a2 = 0.f;

        for (int v0 = vstart; v0 < vend; v0 += 64) {
            int nv = min(64, vend - v0);
            for (int i = t; i < nv * 3;  i += 384) sB[i]  = brow[v0 * 3 + i];
            for (int i = t; i < nv * 16; i += 384) sW[i]  = wts[v0 * 16 + i];
            for (int i = t; i < nv * 21; i += 384) sJr[i] = Jr[v0 * 21 + i];
            __syncthreads();
            if (active) {
                #pragma unroll 2
                for (int v = 0; v < nv; v++) {
                    float p = sW[v * 16 + j] * sJr[v * 21 + k];
                    a0 = fmaf(p, sB[v * 3 + 0], a0);
                    a1 = fmaf(p, sB[v * 3 + 1], a1);
                    a2 = fmaf(p, sB[v * 3 + 2], a2);
                }
            }
            __syncthreads();
        }
        if (active) {
            float* dst = g_Cp + ((size_t)vs * 146 + f) * 1008 + t * 3;
            dst[0] = a0; dst[1] = a1; dst[2] = a2;
        }
    } else {
        int gw   = (bid - 146 * NVS) * 12 + (t >> 5);    // 0..863
        int lane = t & 31;
        float acc = 0.f;
        if (gw < 480) {                 // Js[s][j][c]
            int s = gw / 48, r = gw % 48, j = r / 3, c = r % 3;
            for (int v = lane; v < NV; v += 32)
                acc = fmaf(Jr[v * 21 + j], sd[s * 2334 + v * 3 + c], acc);
        } else if (gw < 528) {          // J0[j][c]
            int idx = gw - 480, j = idx / 3, c = idx % 3;
            for (int v = lane; v < NV; v += 32)
                acc = fmaf(Jr[v * 21 + j], vt[v * 3 + c], acc);
        } else {                        // W[k][j]
            int idx = gw - 528, k = idx / 16, j = idx % 16;
            for (int v = lane; v < NV; v += 32)
                acc = fmaf(Jr[v * 21 + k], wts[v * 16 + j], acc);
        }
        #pragma unroll
        for (int off = 16; off > 0; off >>= 1)
            acc += __shfl_down_sync(0xffffffffu, acc, off);
        if (lane == 0) {
            if (gw < 480)      g_Js[gw] = acc;
            else if (gw < 528) g_J0[gw - 480] = acc;
            else               g_W[gw - 528] = acc;
        }
    }
}

// =====================================================================
// Kernel 1b: combine C partials -> bf16 hi/lo triple rows of g_Cb.
// =====================================================================
__global__ __launch_bounds__(256) void precomp_combine()
{
    int idx = blockIdx.x * 256 + threadIdx.x;   // (f, o336)
    if (idx >= 146 * 336) return;
    int f = idx / 336, o = idx % 336;
    #pragma unroll
    for (int c = 0; c < 3; c++) {
        int o3 = o * 3 + c;
        float v = g_Cp[(size_t)f * 1008 + o3]
                + g_Cp[((size_t)146 + f) * 1008 + o3]
                + g_Cp[((size_t)292 + f) * 1008 + o3]
                + g_Cp[((size_t)438 + f) * 1008 + o3];
        __nv_bfloat16 ch = __float2bfloat16(v);
        __nv_bfloat16 cl = __float2bfloat16(v - __bfloat162float(ch));
        g_Cb[(size_t)f * NP + o3]         = ch;
        g_Cb[(size_t)(160 + f) * NP + o3] = ch;
        g_Cb[(size_t)(320 + f) * NP + o3] = cl;
    }
}

// =====================================================================
// Kernel 2: per-batch forward kinematics. One warp per batch.
// Produces g_Xh[b][512] (hi/lo bf16) and g_A[b][16][12].
// =====================================================================
__global__ __launch_bounds__(256) void fk_kernel(
    const float* __restrict__ beta, const float* __restrict__ theta,
    const float* __restrict__ wrist, const float* __restrict__ hc,
    const float* __restrict__ hm)
{
    __shared__ float sE[8][48];
    __shared__ float sR[8][16][9];
    __shared__ float sJ[8][16][3];
    __shared__ float sG[8][16][12];

    int w = threadIdx.x >> 5, lane = threadIdx.x & 31;
    int b = blockIdx.x * 8 + w;
    __nv_bfloat16* xrow = g_Xh + (size_t)b * KC;

    for (int e = lane; e < 45; e += 32) {
        float v = hm[e];
        #pragma unroll
        for (int s = 0; s < 10; s++)
            v = fmaf(theta[b * 10 + s], hc[s * 45 + e], v);
        sE[w][e] = v;
    }
    __syncwarp();

    if (lane < 16) {
        float r0, r1, r2;
        if (lane == 0) { r0 = wrist[b * 3]; r1 = wrist[b * 3 + 1]; r2 = wrist[b * 3 + 2]; }
        else { int e = (lane - 1) * 3; r0 = sE[w][e]; r1 = sE[w][e + 1]; r2 = sE[w][e + 2]; }
        float t0 = r0 + 1e-8f, t1 = r1 + 1e-8f, t2 = r2 + 1e-8f;
        float ang = sqrtf(t0 * t0 + t1 * t1 + t2 * t2);
        float inv = 1.0f / ang;
        float x = r0 * inv, y = r1 * inv, z = r2 * inv;
        float s, c;
        sincosf(ang, &s, &c);
        float ic = 1.0f - c;
        float R[9];
        R[0] = 1.0f - ic * (y * y + z * z);
        R[1] = -s * z + ic * x * y;
        R[2] =  s * y + ic * x * z;
        R[3] =  s * z + ic * x * y;
        R[4] = 1.0f - ic * (x * x + z * z);
        R[5] = -s * x + ic * y * z;
        R[6] = -s * y + ic * x * z;
        R[7] =  s * x + ic * y * z;
        R[8] = 1.0f - ic * (x * x + y * y);
        #pragma unroll
        for (int m = 0; m < 9; m++) sR[w][lane][m] = R[m];
        if (lane >= 1) {
            int s0 = 11 + (lane - 1) * 9;
            #pragma unroll
            for (int m = 0; m < 9; m++)
                write_hl(xrow, s0 + m, R[m] - ((m == 0 || m == 4 || m == 8) ? 1.0f : 0.0f));
        }
    }
    if (lane == 0)  write_hl(xrow, 0, 1.0f);
    if (lane < 10)  write_hl(xrow, 1 + lane, beta[b * 10 + lane]);

    if (lane < 16) {
        float jx = g_J0[lane * 3 + 0], jy = g_J0[lane * 3 + 1], jz = g_J0[lane * 3 + 2];
        #pragma unroll
        for (int s = 0; s < 10; s++) {
            float bs = beta[b * 10 + s];
            jx = fmaf(bs, g_Js[s * 48 + lane * 3 + 0], jx);
            jy = fmaf(bs, g_Js[s * 48 + lane * 3 + 1], jy);
            jz = fmaf(bs, g_Js[s * 48 + lane * 3 + 2], jz);
        }
        sJ[w][lane][0] = jx; sJ[w][lane][1] = jy; sJ[w][lane][2] = jz;
    }
    __syncwarp();

    if (lane == 0) {
        #pragma unroll
        for (int c = 0; c < 3; c++) {
            #pragma unroll
            for (int d = 0; d < 3; d++) sG[w][0][c * 4 + d] = sR[w][0][c * 3 + d];
            sG[w][0][c * 4 + 3] = sJ[w][0][c];
        }
    }
    __syncwarp();

    if (lane < 5) {
        float pr[9], pt[3];
        #pragma unroll
        for (int c = 0; c < 3; c++) {
            #pragma unroll
            for (int d = 0; d < 3; d++) pr[c * 3 + d] = sG[w][0][c * 4 + d];
            pt[c] = sG[w][0][c * 4 + 3];
        }
        int p = 0;
        #pragma unroll
        for (int st = 0; st < 3; st++) {
            int j = 1 + lane * 3 + st;
            float rj[9];
            #pragma unroll
            for (int m = 0; m < 9; m++) rj[m] = sR[w][j][m];
            float nr[9], nt[3];
            #pragma unroll
            for (int c = 0; c < 3; c++)
                #pragma unroll
                for (int d = 0; d < 3; d++)
                    nr[c * 3 + d] = pr[c * 3 + 0] * rj[0 * 3 + d]
                                  + pr[c * 3 + 1] * rj[1 * 3 + d]
                                  + pr[c * 3 + 2] * rj[2 * 3 + d];
            float dx = sJ[w][j][0] - sJ[w][p][0];
            float dy = sJ[w][j][1] - sJ[w][p][1];
            float dz = sJ[w][j][2] - sJ[w][p][2];
            #pragma unroll
            for (int c = 0; c < 3; c++)
                nt[c] = pr[c * 3 + 0] * dx + pr[c * 3 + 1] * dy + pr[c * 3 + 2] * dz + pt[c];
            #pragma unroll
            for (int c = 0; c < 3; c++) {
                #pragma unroll
                for (int d = 0; d < 3; d++) sG[w][j][c * 4 + d] = nr[c * 3 + d];
                sG[w][j][c * 4 + 3] = nt[c];
            }
            #pragma unroll
            for (int m = 0; m < 9; m++) pr[m] = nr[m];
            pt[0] = nt[0]; pt[1] = nt[1]; pt[2] = nt[2];
            p = j;
        }
    }
    __syncwarp();

    if (lane < 16) {
        float jx = sJ[w][lane][0], jy = sJ[w][lane][1], jz = sJ[w][lane][2];
        #pragma unroll
        for (int c = 0; c < 3; c++) {
            float a0 = sG[w][lane][c * 4 + 0];
            float a1 = sG[w][lane][c * 4 + 1];
            float a2 = sG[w][lane][c * 4 + 2];
            float at = sG[w][lane][c * 4 + 3] - (a0 * jx + a1 * jy + a2 * jz);
            int base = b * 192 + lane * 12 + c * 4;
            g_A[base + 0] = a0; g_A[base + 1] = a1;
            g_A[base + 2] = a2; g_A[base + 3] = at;
        }
    }
}

// =====================================================================
// Kernel 3: bf16 mma.sync GEMM  M[8192,1024] = Xh[8192,480] * Cb[480,1024]
// CTA tile 128x128, BK=32, 3-stage cp.async pipeline, warp tile 64x32.
// =====================================================================
__global__ __launch_bounds__(256) void mma_kernel()
{
    __shared__ __align__(128) __nv_bfloat16 smA[3][128 * BKC];   // [st][m][k] 64B rows
    __shared__ __align__(128) __nv_bfloat16 smB[3][BKC * 128];   // [st][k][n] 256B rows

    const int tid = threadIdx.x;
    const int wid = tid >> 5, lane = tid & 31;
    const int bn0 = blockIdx.x * 128;
    const int bm0 = blockIdx.y * 128;
    const int warp_m = (wid & 1) * 64;
    const int warp_n = (wid >> 1) * 32;

    const uint32_t smA_u = (uint32_t)__cvta_generic_to_shared(&smA[0][0]);
    const uint32_t smB_u = (uint32_t)__cvta_generic_to_shared(&smB[0][0]);

    float acc[4][4][4];
    #pragma unroll
    for (int mt = 0; mt < 4; mt++)
        #pragma unroll
        for (int nt = 0; nt < 4; nt++)
            #pragma unroll
            for (int q = 0; q < 4; q++) acc[mt][nt][q] = 0.f;

    auto load_chunk = [&](int kc, int st) {
        #pragma unroll
        for (int i = 0; i < 2; i++) {
            int idx = i * 256 + tid;
            int row = idx >> 2, c16 = idx & 3;
            uint32_t off = SWA((uint32_t)(row * 64 + c16 * 16));
            cp16(smA_u + st * 8192 + off,
                 g_Xh + (size_t)(bm0 + row) * KC + kc * BKC + c16 * 8);
        }
        #pragma unroll
        for (int i = 0; i < 2; i++) {
            int idx = i * 256 + tid;
            int row = idx >> 4, c16 = idx & 15;
            uint32_t off = SWB((uint32_t)(row * 256 + c16 * 16));
            cp16(smB_u + st * 8192 + off,
                 g_Cb + (size_t)(kc * BKC + row) * NP + bn0 + c16 * 8);
        }
    };

    load_chunk(0, 0); CP_COMMIT();
    load_chunk(1, 1); CP_COMMIT();

    const int r15 = lane & 15;
    const int kq  = lane >> 4;

    #pragma unroll 1
    for (int kc = 0; kc < NCH; kc++) {
        CP_WAIT1();
        __syncthreads();
        int nk = kc + 2;
        if (nk < NCH) load_chunk(nk, nk % 3);
        CP_COMMIT();

        int st = kc % 3;
        #pragma unroll
        for (int ks = 0; ks < 2; ks++) {
            uint32_t a[4][4], b[4][2];
            #pragma unroll
            for (int mt = 0; mt < 4; mt++) {
                uint32_t off = (uint32_t)((warp_m + mt * 16 + r15) * 64
                                          + (ks * 16 + kq * 8) * 2);
                ldsm_x4(a[mt], smA_u + st * 8192 + SWA(off));
            }
            #pragma unroll
            for (int nt = 0; nt < 4; nt++) {
                uint32_t off = (uint32_t)((ks * 16 + r15) * 256
                                          + (warp_n + nt * 8) * 2);
                ldsm_x2_t(b[nt], smB_u + st * 8192 + SWB(off));
            }
            #pragma unroll
            for (int mt = 0; mt < 4; mt++)
                #pragma unroll
                for (int nt = 0; nt < 4; nt++)
                    mma16816(acc[mt][nt], a[mt], b[nt]);
        }
    }

    // epilogue: lane l owns rows (l>>2, +8), cols (l&3)*2 within each 16x8 tile
    #pragma unroll
    for (int mt = 0; mt < 4; mt++) {
        #pragma unroll
        for (int nt = 0; nt < 4; nt++) {
            int r0 = bm0 + warp_m + mt * 16 + (lane >> 2);
            int c  = bn0 + warp_n + nt * 8 + (lane & 3) * 2;
            float2 v0 = make_float2(acc[mt][nt][0], acc[mt][nt][1]);
            float2 v1 = make_float2(acc[mt][nt][2], acc[mt][nt][3]);
            *(float2*)&g_M[(size_t)r0 * NP + c] = v0;
            *(float2*)&g_M[(size_t)(r0 + 8) * NP + c] = v1;
        }
    }
}

// =====================================================================
// Kernel 4: joints[b,k,c] = sum_j ( A[b,j,c,:3].M[b,j,k,:] + A[b,j,c,3]*W[k,j] )
// One warp per batch, M staged through shared memory. (R4-proven form.)
// =====================================================================
__global__ __launch_bounds__(256) void reduce_kernel(float* __restrict__ out)
{
    __shared__ float Msh[8][1008];
    __shared__ float Ash[8][192];
    __shared__ float Wsh[336];

    int w = threadIdx.x >> 5, lane = threadIdx.x & 31;
    int b = blockIdx.x * 8 + w;

    for (int i = threadIdx.x; i < 336; i += 256) Wsh[i] = g_W[i];
    #pragma unroll
    for (int r = 0; r < 8; r++) {
        int idx = lane + r * 32;
        if (idx < 252)
            *(float4*)&Msh[w][idx * 4] = *(const float4*)&g_M[(size_t)b * NP + idx * 4];
    }
    #pragma unroll
    for (int r = 0; r < 2; r++) {
        int idx = lane + r * 32;
        if (idx < 48)
            *(float4*)&Ash[w][idx * 4] = *(const float4*)&g_A[b * 192 + idx * 4];
    }
    __syncthreads();

    #pragma unroll
    for (int rep = 0; rep < 2; rep++) {
        int o = lane + rep * 32;
        if (o < 63) {
            int k = o / 3, c = o % 3;
            float acc = 0.f;
            #pragma unroll
            for (int j = 0; j < 16; j++) {
                const float* a = &Ash[w][j * 12 + c * 4];
                const float* m = &Msh[w][(j * 21 + k) * 3];
                acc = fmaf(a[0], m[0], acc);
                acc = fmaf(a[1], m[1], acc);
                acc = fmaf(a[2], m[2], acc);
                acc = fmaf(a[3], Wsh[k * 16 + j], acc);
            }
            out[b * 63 + o] = acc;
        }
    }
}

// =====================================================================
extern "C" void kernel_launch(void* const* d_in, const int* in_sizes, int n_in,
                              void* d_out, int out_size)
{
    const float* beta  = (const float*)d_in[0];
    const float* theta = (const float*)d_in[1];
    const float* wrist = (const float*)d_in[2];
    const float* vt    = (const float*)d_in[3];
    const float* sd    = (const float*)d_in[4];
    const float* pd    = (const float*)d_in[5];
    const float* Jr    = (const float*)d_in[6];
    const float* hc    = (const float*)d_in[7];
    const float* hm    = (const float*)d_in[8];
    const float* wts   = (const float*)d_in[9];
    float* out = (float*)d_out;

    precomp_part<<<146 * NVS + 72, 384>>>(vt, sd, pd, Jr, wts);
    precomp_combine<<<192, 256>>>();
    fk_kernel<<<1024, 256>>>(beta, theta, wrist, hc, hm);
    mma_kernel<<<dim3(NP / 128, NB / 128), 256>>>();
    reduce_kernel<<<1024, 256>>>(out);
}

// round 7
// speedup vs baseline: 1.8497x; 1.0264x over previous
#include <cuda_runtime.h>
#include <cuda_bf16.h>
#include <math.h>
#include <stdint.h>

// Problem constants
#define NB   8192          // batch
#define NV   778           // vertices
#define KC   512           // padded K stride (3x160 split: [Xhi|Xlo|Xhi] vs [Chi|Chi|Clo])
#define NP   1024          // padded N
#define BKC  32            // k per pipeline chunk
#define NCH  15            // 480 / 32 used chunks
#define NVS  8             // vertex splits for precomp_C
#define VPB  98            // verts per split block

// ---------------- scratch (device globals; zero-initialized at load) ----------------
__device__ __nv_bfloat16 g_Xh[(size_t)NB * KC];   // [b][k]  A operand bf16
__device__ __nv_bfloat16 g_Cb[(size_t)KC * NP];   // [k][o]  B operand bf16
__device__ float  g_Cp[NVS * 146 * 1008];         // fp32 partials of C
__device__ float  g_A[NB * 192];                  // [b][j][3x4]
__device__ float  g_M[(size_t)NB * NP];           // GEMM output [b][o]
__device__ float  g_Js[480];
__device__ float  g_J0[48];
__device__ float  g_W[336];

// ---------------- helpers ----------------
__device__ __forceinline__ void write_hl(__nv_bfloat16* base, int s, float v) {
    __nv_bfloat16 h = __float2bfloat16(v);
    __nv_bfloat16 l = __float2bfloat16(v - __bfloat162float(h));
    base[s] = h; base[160 + s] = l; base[320 + s] = h;
}
__device__ __forceinline__ void ldsm_x4(uint32_t* r, uint32_t addr) {
    asm volatile("ldmatrix.sync.aligned.m8n8.x4.shared.b16 {%0,%1,%2,%3}, [%4];"
                 : "=r"(r[0]), "=r"(r[1]), "=r"(r[2]), "=r"(r[3]) : "r"(addr));
}
__device__ __forceinline__ void ldsm_x2_t(uint32_t* r, uint32_t addr) {
    asm volatile("ldmatrix.sync.aligned.m8n8.x2.trans.shared.b16 {%0,%1}, [%2];"
                 : "=r"(r[0]), "=r"(r[1]) : "r"(addr));
}
__device__ __forceinline__ void mma16816(float* d, const uint32_t* a, const uint32_t* b) {
    asm volatile("mma.sync.aligned.m16n8k16.row.col.f32.bf16.bf16.f32 "
                 "{%0,%1,%2,%3}, {%4,%5,%6,%7}, {%8,%9}, {%0,%1,%2,%3};"
                 : "+f"(d[0]), "+f"(d[1]), "+f"(d[2]), "+f"(d[3])
                 : "r"(a[0]), "r"(a[1]), "r"(a[2]), "r"(a[3]), "r"(b[0]), "r"(b[1]));
}
__device__ __forceinline__ void cp16(uint32_t saddr, const void* g) {
    asm volatile("cp.async.cg.shared.global [%0], [%1], 16;" :: "r"(saddr), "l"(g) : "memory");
}
#define CP_COMMIT() asm volatile("cp.async.commit_group;" ::: "memory")
#define CP_WAIT1()  asm volatile("cp.async.wait_group 1;" ::: "memory")
// A staging: 64B rows (32 halfs), swizzle bits[5:4] ^= bits[7:6]
#define SWA(o) ((o) ^ (((o) >> 2) & 0x30))
// B staging: 256B rows (128 halfs), swizzle bits[6:4] ^= bits[10:8]
#define SWB(o) ((o) ^ (((o) >> 4) & 0x70))

// =====================================================================
// Kernel 1: precomp_part — blocks 0..1167: C partials over 8 vertex splits;
//           blocks 1168..1239: small reductions (Js, J0, W).
// =====================================================================
__global__ __launch_bounds__(384) void precomp_part(
    const float* __restrict__ vt, const float* __restrict__ sd,
    const float* __restrict__ pd, const float* __restrict__ Jr,
    const float* __restrict__ wts)
{
    __shared__ float sB[64 * 3];
    __shared__ float sW[64 * 16];
    __shared__ float sJr[64 * 21];

    int t = threadIdx.x;
    int bid = blockIdx.x;

    if (bid < 146 * NVS) {
        int f  = bid >> 3;
        int vs = bid & 7;
        const float* brow = (f == 0) ? vt : ((f <= 10) ? (sd + (f - 1) * 2334)
                                                       : (pd + (f - 11) * 2334));
        int vstart = vs * VPB;
        int vend   = min(NV, vstart + VPB);
        int j = t / 21, k = t % 21;
        bool active = (t < 336);
        float a0 = 0.f, a1 = 0.f, a2 = 0.f;

        for (int v0 = vstart; v0 < vend; v0 += 64) {
            int nv = min(64, vend - v0);
            for (int i = t; i < nv * 3;  i += 384) sB[i]  = brow[v0 * 3 + i];
            for (int i = t; i < nv * 16; i += 384) sW[i]  = wts[v0 * 16 + i];
            for (int i = t; i < nv * 21; i += 384) sJr[i] = Jr[v0 * 21 + i];
            __syncthreads();
            if (active) {
                #pragma unroll 2
                for (int v = 0; v < nv; v++) {
                    float p = sW[v * 16 + j] * sJr[v * 21 + k];
                    a0 = fmaf(p, sB[v * 3 + 0], a0);
                    a1 = fmaf(p, sB[v * 3 + 1], a1);
                    a2 = fmaf(p, sB[v * 3 + 2], a2);
                }
            }
            __syncthreads();
        }
        if (active) {
            float* dst = g_Cp + ((size_t)vs * 146 + f) * 1008 + t * 3;
            dst[0] = a0; dst[1] = a1; dst[2] = a2;
        }
    } else {
        int gw   = (bid - 146 * NVS) * 12 + (t >> 5);    // 0..863
        int lane = t & 31;
        float acc = 0.f;
        if (gw < 480) {                 // Js[s][j][c]
            int s = gw / 48, r = gw % 48, j = r / 3, c = r % 3;
            for (int v = lane; v < NV; v += 32)
                acc = fmaf(Jr[v * 21 + j], sd[s * 2334 + v * 3 + c], acc);
        } else if (gw < 528) {          // J0[j][c]
            int idx = gw - 480, j = idx / 3, c = idx % 3;
            for (int v = lane; v < NV; v += 32)
                acc = fmaf(Jr[v * 21 + j], vt[v * 3 + c], acc);
        } else {                        // W[k][j]
            int idx = gw - 528, k = idx / 16, j = idx % 16;
            for (int v = lane; v < NV; v += 32)
                acc = fmaf(Jr[v * 21 + k], wts[v * 16 + j], acc);
        }
        #pragma unroll
        for (int off = 16; off > 0; off >>= 1)
            acc += __shfl_down_sync(0xffffffffu, acc, off);
        if (lane == 0) {
            if (gw < 480)      g_Js[gw] = acc;
            else if (gw < 528) g_J0[gw - 480] = acc;
            else               g_W[gw - 528] = acc;
        }
    }
}

// =====================================================================
// Kernel 1b: combine C partials -> bf16 hi/lo triple rows of g_Cb.
// =====================================================================
__global__ __launch_bounds__(256) void precomp_combine()
{
    int idx = blockIdx.x * 256 + threadIdx.x;   // (f, o336)
    if (idx >= 146 * 336) return;
    int f = idx / 336, o = idx % 336;
    #pragma unroll
    for (int c = 0; c < 3; c++) {
        int o3 = o * 3 + c;
        float v = 0.f;
        #pragma unroll
        for (int vs = 0; vs < NVS; vs++)
            v += g_Cp[((size_t)vs * 146 + f) * 1008 + o3];
        __nv_bfloat16 ch = __float2bfloat16(v);
        __nv_bfloat16 cl = __float2bfloat16(v - __bfloat162float(ch));
        g_Cb[(size_t)f * NP + o3]         = ch;
        g_Cb[(size_t)(160 + f) * NP + o3] = ch;
        g_Cb[(size_t)(320 + f) * NP + o3] = cl;
    }
}

// =====================================================================
// Kernel 2: per-batch forward kinematics. One warp per batch.
// Produces g_Xh[b][512] (hi/lo bf16) and g_A[b][16][12].
// =====================================================================
__global__ __launch_bounds__(256) void fk_kernel(
    const float* __restrict__ beta, const float* __restrict__ theta,
    const float* __restrict__ wrist, const float* __restrict__ hc,
    const float* __restrict__ hm)
{
    __shared__ float sE[8][48];
    __shared__ float sR[8][16][9];
    __shared__ float sJ[8][16][3];
    __shared__ float sG[8][16][12];

    int w = threadIdx.x >> 5, lane = threadIdx.x & 31;
    int b = blockIdx.x * 8 + w;
    __nv_bfloat16* xrow = g_Xh + (size_t)b * KC;

    for (int e = lane; e < 45; e += 32) {
        float v = hm[e];
        #pragma unroll
        for (int s = 0; s < 10; s++)
            v = fmaf(theta[b * 10 + s], hc[s * 45 + e], v);
        sE[w][e] = v;
    }
    __syncwarp();

    if (lane < 16) {
        float r0, r1, r2;
        if (lane == 0) { r0 = wrist[b * 3]; r1 = wrist[b * 3 + 1]; r2 = wrist[b * 3 + 2]; }
        else { int e = (lane - 1) * 3; r0 = sE[w][e]; r1 = sE[w][e + 1]; r2 = sE[w][e + 2]; }
        float t0 = r0 + 1e-8f, t1 = r1 + 1e-8f, t2 = r2 + 1e-8f;
        float ang = sqrtf(t0 * t0 + t1 * t1 + t2 * t2);
        float inv = 1.0f / ang;
        float x = r0 * inv, y = r1 * inv, z = r2 * inv;
        float s, c;
        sincosf(ang, &s, &c);
        float ic = 1.0f - c;
        float R[9];
        R[0] = 1.0f - ic * (y * y + z * z);
        R[1] = -s * z + ic * x * y;
        R[2] =  s * y + ic * x * z;
        R[3] =  s * z + ic * x * y;
        R[4] = 1.0f - ic * (x * x + z * z);
        R[5] = -s * x + ic * y * z;
        R[6] = -s * y + ic * x * z;
        R[7] =  s * x + ic * y * z;
        R[8] = 1.0f - ic * (x * x + y * y);
        #pragma unroll
        for (int m = 0; m < 9; m++) sR[w][lane][m] = R[m];
        if (lane >= 1) {
            int s0 = 11 + (lane - 1) * 9;
            #pragma unroll
            for (int m = 0; m < 9; m++)
                write_hl(xrow, s0 + m, R[m] - ((m == 0 || m == 4 || m == 8) ? 1.0f : 0.0f));
        }
    }
    if (lane == 0)  write_hl(xrow, 0, 1.0f);
    if (lane < 10)  write_hl(xrow, 1 + lane, beta[b * 10 + lane]);

    if (lane < 16) {
        float jx = g_J0[lane * 3 + 0], jy = g_J0[lane * 3 + 1], jz = g_J0[lane * 3 + 2];
        #pragma unroll
        for (int s = 0; s < 10; s++) {
            float bs = beta[b * 10 + s];
            jx = fmaf(bs, g_Js[s * 48 + lane * 3 + 0], jx);
            jy = fmaf(bs, g_Js[s * 48 + lane * 3 + 1], jy);
            jz = fmaf(bs, g_Js[s * 48 + lane * 3 + 2], jz);
        }
        sJ[w][lane][0] = jx; sJ[w][lane][1] = jy; sJ[w][lane][2] = jz;
    }
    __syncwarp();

    if (lane == 0) {
        #pragma unroll
        for (int c = 0; c < 3; c++) {
            #pragma unroll
            for (int d = 0; d < 3; d++) sG[w][0][c * 4 + d] = sR[w][0][c * 3 + d];
            sG[w][0][c * 4 + 3] = sJ[w][0][c];
        }
    }
    __syncwarp();

    if (lane < 5) {
        float pr[9], pt[3];
        #pragma unroll
        for (int c = 0; c < 3; c++) {
            #pragma unroll
            for (int d = 0; d < 3; d++) pr[c * 3 + d] = sG[w][0][c * 4 + d];
            pt[c] = sG[w][0][c * 4 + 3];
        }
        int p = 0;
        #pragma unroll
        for (int st = 0; st < 3; st++) {
            int j = 1 + lane * 3 + st;
            float rj[9];
            #pragma unroll
            for (int m = 0; m < 9; m++) rj[m] = sR[w][j][m];
            float nr[9], nt[3];
            #pragma unroll
            for (int c = 0; c < 3; c++)
                #pragma unroll
                for (int d = 0; d < 3; d++)
                    nr[c * 3 + d] = pr[c * 3 + 0] * rj[0 * 3 + d]
                                  + pr[c * 3 + 1] * rj[1 * 3 + d]
                                  + pr[c * 3 + 2] * rj[2 * 3 + d];
            float dx = sJ[w][j][0] - sJ[w][p][0];
            float dy = sJ[w][j][1] - sJ[w][p][1];
            float dz = sJ[w][j][2] - sJ[w][p][2];
            #pragma unroll
            for (int c = 0; c < 3; c++)
                nt[c] = pr[c * 3 + 0] * dx + pr[c * 3 + 1] * dy + pr[c * 3 + 2] * dz + pt[c];
            #pragma unroll
            for (int c = 0; c < 3; c++) {
                #pragma unroll
                for (int d = 0; d < 3; d++) sG[w][j][c * 4 + d] = nr[c * 3 + d];
                sG[w][j][c * 4 + 3] = nt[c];
            }
            #pragma unroll
            for (int m = 0; m < 9; m++) pr[m] = nr[m];
            pt[0] = nt[0]; pt[1] = nt[1]; pt[2] = nt[2];
            p = j;
        }
    }
    __syncwarp();

    if (lane < 16) {
        float jx = sJ[w][lane][0], jy = sJ[w][lane][1], jz = sJ[w][lane][2];
        #pragma unroll
        for (int c = 0; c < 3; c++) {
            float a0 = sG[w][lane][c * 4 + 0];
            float a1 = sG[w][lane][c * 4 + 1];
            float a2 = sG[w][lane][c * 4 + 2];
            float at = sG[w][lane][c * 4 + 3] - (a0 * jx + a1 * jy + a2 * jz);
            int base = b * 192 + lane * 12 + c * 4;
            g_A[base + 0] = a0; g_A[base + 1] = a1;
            g_A[base + 2] = a2; g_A[base + 3] = at;
        }
    }
}

// =====================================================================
// Kernel 3: bf16 mma.sync GEMM  M[8192,1024] = Xh[8192,480] * Cb[480,1024]
// CTA tile 128x128, BK=32, 3-stage cp.async pipeline, warp tile 64x32.
// =====================================================================
__global__ __launch_bounds__(256) void mma_kernel()
{
    __shared__ __align__(128) __nv_bfloat16 smA[3][128 * BKC];   // [st][m][k] 64B rows
    __shared__ __align__(128) __nv_bfloat16 smB[3][BKC * 128];   // [st][k][n] 256B rows

    const int tid = threadIdx.x;
    const int wid = tid >> 5, lane = tid & 31;
    const int bn0 = blockIdx.x * 128;
    const int bm0 = blockIdx.y * 128;
    const int warp_m = (wid & 1) * 64;
    const int warp_n = (wid >> 1) * 32;

    const uint32_t smA_u = (uint32_t)__cvta_generic_to_shared(&smA[0][0]);
    const uint32_t smB_u = (uint32_t)__cvta_generic_to_shared(&smB[0][0]);

    float acc[4][4][4];
    #pragma unroll
    for (int mt = 0; mt < 4; mt++)
        #pragma unroll
        for (int nt = 0; nt < 4; nt++)
            #pragma unroll
            for (int q = 0; q < 4; q++) acc[mt][nt][q] = 0.f;

    auto load_chunk = [&](int kc, int st) {
        #pragma unroll
        for (int i = 0; i < 2; i++) {
            int idx = i * 256 + tid;
            int row = idx >> 2, c16 = idx & 3;
            uint32_t off = SWA((uint32_t)(row * 64 + c16 * 16));
            cp16(smA_u + st * 8192 + off,
                 g_Xh + (size_t)(bm0 + row) * KC + kc * BKC + c16 * 8);
        }
        #pragma unroll
        for (int i = 0; i < 2; i++) {
            int idx = i * 256 + tid;
            int row = idx >> 4, c16 = idx & 15;
            uint32_t off = SWB((uint32_t)(row * 256 + c16 * 16));
            cp16(smB_u + st * 8192 + off,
                 g_Cb + (size_t)(kc * BKC + row) * NP + bn0 + c16 * 8);
        }
    };

    load_chunk(0, 0); CP_COMMIT();
    load_chunk(1, 1); CP_COMMIT();

    const int r15 = lane & 15;
    const int kq  = lane >> 4;

    #pragma unroll 1
    for (int kc = 0; kc < NCH; kc++) {
        CP_WAIT1();
        __syncthreads();
        int nk = kc + 2;
        if (nk < NCH) load_chunk(nk, nk % 3);
        CP_COMMIT();

        int st = kc % 3;
        #pragma unroll
        for (int ks = 0; ks < 2; ks++) {
            uint32_t a[4][4], b[4][2];
            #pragma unroll
            for (int mt = 0; mt < 4; mt++) {
                uint32_t off = (uint32_t)((warp_m + mt * 16 + r15) * 64
                                          + (ks * 16 + kq * 8) * 2);
                ldsm_x4(a[mt], smA_u + st * 8192 + SWA(off));
            }
            #pragma unroll
            for (int nt = 0; nt < 4; nt++) {
                uint32_t off = (uint32_t)((ks * 16 + r15) * 256
                                          + (warp_n + nt * 8) * 2);
                ldsm_x2_t(b[nt], smB_u + st * 8192 + SWB(off));
            }
            #pragma unroll
            for (int mt = 0; mt < 4; mt++)
                #pragma unroll
                for (int nt = 0; nt < 4; nt++)
                    mma16816(acc[mt][nt], a[mt], b[nt]);
        }
    }

    // epilogue: lane l owns rows (l>>2, +8), cols (l&3)*2 within each 16x8 tile
    #pragma unroll
    for (int mt = 0; mt < 4; mt++) {
        #pragma unroll
        for (int nt = 0; nt < 4; nt++) {
            int r0 = bm0 + warp_m + mt * 16 + (lane >> 2);
            int c  = bn0 + warp_n + nt * 8 + (lane & 3) * 2;
            float2 v0 = make_float2(acc[mt][nt][0], acc[mt][nt][1]);
            float2 v1 = make_float2(acc[mt][nt][2], acc[mt][nt][3]);
            *(float2*)&g_M[(size_t)r0 * NP + c] = v0;
            *(float2*)&g_M[(size_t)(r0 + 8) * NP + c] = v1;
        }
    }
}

// =====================================================================
// Kernel 4: joints[b,k,c] = sum_j ( A[b,j,c,:3].M[b,j,k,:] + A[b,j,c,3]*W[k,j] )
// One warp per batch; M read DIRECTLY from global (L2-resident), no staging.
// =====================================================================
__global__ __launch_bounds__(256) void reduce_kernel(float* __restrict__ out)
{
    __shared__ float Ash[8][192];
    __shared__ float Wsh[336];

    int w = threadIdx.x >> 5, lane = threadIdx.x & 31;
    int b = blockIdx.x * 8 + w;

    for (int i = threadIdx.x; i < 336; i += 256) Wsh[i] = g_W[i];
    for (int i = threadIdx.x; i < 384; i += 256)
        ((float4*)&Ash[0][0])[i] = ((const float4*)&g_A[blockIdx.x * 8 * 192])[i];
    __syncthreads();

    const float* mrow = g_M + (size_t)b * NP;

    #pragma unroll
    for (int rep = 0; rep < 2; rep++) {
        int o = lane + rep * 32;
        if (o < 63) {
            int k = o / 3, c = o % 3;
            float acc = 0.f;
            #pragma unroll
            for (int j = 0; j < 16; j++) {
                const float* a = &Ash[w][j * 12 + c * 4];
                const float* m = mrow + j * 63 + k * 3;
                acc = fmaf(a[0], __ldg(m + 0), acc);
                acc = fmaf(a[1], __ldg(m + 1), acc);
                acc = fmaf(a[2], __ldg(m + 2), acc);
                acc = fmaf(a[3], Wsh[k * 16 + j], acc);
            }
            out[b * 63 + o] = acc;
        }
    }
}

// =====================================================================
extern "C" void kernel_launch(void* const* d_in, const int* in_sizes, int n_in,
                              void* d_out, int out_size)
{
    const float* beta  = (const float*)d_in[0];
    const float* theta = (const float*)d_in[1];
    const float* wrist = (const float*)d_in[2];
    const float* vt    = (const float*)d_in[3];
    const float* sd    = (const float*)d_in[4];
    const float* pd    = (const float*)d_in[5];
    const float* Jr    = (const float*)d_in[6];
    const float* hc    = (const float*)d_in[7];
    const float* hm    = (const float*)d_in[8];
    const float* wts   = (const float*)d_in[9];
    float* out = (float*)d_out;

    precomp_part<<<146 * NVS + 72, 384>>>(vt, sd, pd, Jr, wts);
    precomp_combine<<<192, 256>>>();
    fk_kernel<<<1024, 256>>>(beta, theta, wrist, hc, hm);
    mma_kernel<<<dim3(NP / 128, NB / 128), 256>>>();
    reduce_kernel<<<1024, 256>>>(out);
}

// round 8
// speedup vs baseline: 1.9078x; 1.0314x over previous
#include <cuda_runtime.h>
#include <cuda_bf16.h>
#include <math.h>
#include <stdint.h>

// Problem constants
#define NB   8192          // batch
#define NV   778           // vertices
#define KC   512           // padded K stride (3x160 split: [Xhi|Xlo|Xhi] vs [Chi|Chi|Clo])
#define NP   1024          // padded N
#define BKC  32            // k per pipeline chunk
#define NCH  15            // 480 / 32 used chunks
#define NVS  8             // vertex splits for precomp_C
#define VPB  98            // verts per split block

// ---------------- scratch (device globals; zero-initialized at load) ----------------
__device__ __nv_bfloat16 g_Xh[(size_t)NB * KC];   // [b][k]  A operand bf16
__device__ __nv_bfloat16 g_Cb[(size_t)KC * NP];   // [k][o]  B operand bf16
__device__ float  g_Cp[NVS * 146 * 1008];         // fp32 partials of C
__device__ float  g_A[NB * 192];                  // [b][j][3x4]
__device__ float  g_M[(size_t)NB * NP];           // GEMM output [b][o]
__device__ float  g_Js[480];
__device__ float  g_J0[48];
__device__ float  g_W[336];

// ---------------- helpers ----------------
__device__ __forceinline__ void write_hl(__nv_bfloat16* base, int s, float v) {
    __nv_bfloat16 h = __float2bfloat16(v);
    __nv_bfloat16 l = __float2bfloat16(v - __bfloat162float(h));
    base[s] = h; base[160 + s] = l; base[320 + s] = h;
}
__device__ __forceinline__ void ldsm_x4(uint32_t* r, uint32_t addr) {
    asm volatile("ldmatrix.sync.aligned.m8n8.x4.shared.b16 {%0,%1,%2,%3}, [%4];"
                 : "=r"(r[0]), "=r"(r[1]), "=r"(r[2]), "=r"(r[3]) : "r"(addr));
}
__device__ __forceinline__ void ldsm_x2_t(uint32_t* r, uint32_t addr) {
    asm volatile("ldmatrix.sync.aligned.m8n8.x2.trans.shared.b16 {%0,%1}, [%2];"
                 : "=r"(r[0]), "=r"(r[1]) : "r"(addr));
}
__device__ __forceinline__ void mma16816(float* d, const uint32_t* a, const uint32_t* b) {
    asm volatile("mma.sync.aligned.m16n8k16.row.col.f32.bf16.bf16.f32 "
                 "{%0,%1,%2,%3}, {%4,%5,%6,%7}, {%8,%9}, {%0,%1,%2,%3};"
                 : "+f"(d[0]), "+f"(d[1]), "+f"(d[2]), "+f"(d[3])
                 : "r"(a[0]), "r"(a[1]), "r"(a[2]), "r"(a[3]), "r"(b[0]), "r"(b[1]));
}
__device__ __forceinline__ void cp16(uint32_t saddr, const void* g) {
    asm volatile("cp.async.cg.shared.global [%0], [%1], 16;" :: "r"(saddr), "l"(g) : "memory");
}
#define CP_COMMIT() asm volatile("cp.async.commit_group;" ::: "memory")
#define CP_WAIT1()  asm volatile("cp.async.wait_group 1;" ::: "memory")
// A staging: 64B rows (32 halfs), swizzle bits[5:4] ^= bits[7:6]
#define SWA(o) ((o) ^ (((o) >> 2) & 0x30))
// B staging: 256B rows (128 halfs), swizzle bits[6:4] ^= bits[10:8]
#define SWB(o) ((o) ^ (((o) >> 4) & 0x70))

// =====================================================================
// Kernel 1: precomp_part — blocks 0..1167: C partials over 8 vertex splits;
//           blocks 1168..1239: small reductions (Js, J0, W).
// =====================================================================
__global__ __launch_bounds__(384) void precomp_part(
    const float* __restrict__ vt, const float* __restrict__ sd,
    const float* __restrict__ pd, const float* __restrict__ Jr,
    const float* __restrict__ wts)
{
    __shared__ float sB[64 * 3];
    __shared__ float sW[64 * 16];
    __shared__ float sJr[64 * 21];

    int t = threadIdx.x;
    int bid = blockIdx.x;

    if (bid < 146 * NVS) {
        int f  = bid >> 3;
        int vs = bid & 7;
        const float* brow = (f == 0) ? vt : ((f <= 10) ? (sd + (f - 1) * 2334)
                                                       : (pd + (f - 11) * 2334));
        int vstart = vs * VPB;
        int vend   = min(NV, vstart + VPB);
        int j = t / 21, k = t % 21;
        bool active = (t < 336);
        float a0 = 0.f, a1 = 0.f, a2 = 0.f;

        for (int v0 = vstart; v0 < vend; v0 += 64) {
            int nv = min(64, vend - v0);
            for (int i = t; i < nv * 3;  i += 384) sB[i]  = brow[v0 * 3 + i];
            for (int i = t; i < nv * 16; i += 384) sW[i]  = wts[v0 * 16 + i];
            for (int i = t; i < nv * 21; i += 384) sJr[i] = Jr[v0 * 21 + i];
            __syncthreads();
            if (active) {
                #pragma unroll 2
                for (int v = 0; v < nv; v++) {
                    float p = sW[v * 16 + j] * sJr[v * 21 + k];
                    a0 = fmaf(p, sB[v * 3 + 0], a0);
                    a1 = fmaf(p, sB[v * 3 + 1], a1);
                    a2 = fmaf(p, sB[v * 3 + 2], a2);
                }
            }
            __syncthreads();
        }
        if (active) {
            float* dst = g_Cp + ((size_t)vs * 146 + f) * 1008 + t * 3;
            dst[0] = a0; dst[1] = a1; dst[2] = a2;
        }
    } else {
        int gw   = (bid - 146 * NVS) * 12 + (t >> 5);    // 0..863
        int lane = t & 31;
        float acc = 0.f;
        if (gw < 480) {                 // Js[s][j][c]
            int s = gw / 48, r = gw % 48, j = r / 3, c = r % 3;
            for (int v = lane; v < NV; v += 32)
                acc = fmaf(Jr[v * 21 + j], sd[s * 2334 + v * 3 + c], acc);
        } else if (gw < 528) {          // J0[j][c]
            int idx = gw - 480, j = idx / 3, c = idx % 3;
            for (int v = lane; v < NV; v += 32)
                acc = fmaf(Jr[v * 21 + j], vt[v * 3 + c], acc);
        } else {                        // W[k][j]
            int idx = gw - 528, k = idx / 16, j = idx % 16;
            for (int v = lane; v < NV; v += 32)
                acc = fmaf(Jr[v * 21 + k], wts[v * 16 + j], acc);
        }
        #pragma unroll
        for (int off = 16; off > 0; off >>= 1)
            acc += __shfl_down_sync(0xffffffffu, acc, off);
        if (lane == 0) {
            if (gw < 480)      g_Js[gw] = acc;
            else if (gw < 528) g_J0[gw - 480] = acc;
            else               g_W[gw - 528] = acc;
        }
    }
}

// =====================================================================
// Kernel 2: fk_kernel — blocks 0..1023: per-batch forward kinematics
//           (one warp per batch -> g_Xh, g_A);
//           blocks 1024..1215: combine C partials -> bf16 hi/lo g_Cb.
// Both halves depend only on precomp_part.
// =====================================================================
__global__ __launch_bounds__(256) void fk_kernel(
    const float* __restrict__ beta, const float* __restrict__ theta,
    const float* __restrict__ wrist, const float* __restrict__ hc,
    const float* __restrict__ hm)
{
    if (blockIdx.x >= 1024) {
        // ---- combine C partials ----
        int idx = (blockIdx.x - 1024) * 256 + threadIdx.x;   // (f, o336)
        if (idx >= 146 * 336) return;
        int f = idx / 336, o = idx % 336;
        #pragma unroll
        for (int c = 0; c < 3; c++) {
            int o3 = o * 3 + c;
            float v = 0.f;
            #pragma unroll
            for (int vs = 0; vs < NVS; vs++)
                v += g_Cp[((size_t)vs * 146 + f) * 1008 + o3];
            __nv_bfloat16 ch = __float2bfloat16(v);
            __nv_bfloat16 cl = __float2bfloat16(v - __bfloat162float(ch));
            g_Cb[(size_t)f * NP + o3]         = ch;
            g_Cb[(size_t)(160 + f) * NP + o3] = ch;
            g_Cb[(size_t)(320 + f) * NP + o3] = cl;
        }
        return;
    }

    __shared__ float sE[8][48];
    __shared__ float sR[8][16][9];
    __shared__ float sJ[8][16][3];
    __shared__ float sG[8][16][12];

    int w = threadIdx.x >> 5, lane = threadIdx.x & 31;
    int b = blockIdx.x * 8 + w;
    __nv_bfloat16* xrow = g_Xh + (size_t)b * KC;

    for (int e = lane; e < 45; e += 32) {
        float v = hm[e];
        #pragma unroll
        for (int s = 0; s < 10; s++)
            v = fmaf(theta[b * 10 + s], hc[s * 45 + e], v);
        sE[w][e] = v;
    }
    __syncwarp();

    if (lane < 16) {
        float r0, r1, r2;
        if (lane == 0) { r0 = wrist[b * 3]; r1 = wrist[b * 3 + 1]; r2 = wrist[b * 3 + 2]; }
        else { int e = (lane - 1) * 3; r0 = sE[w][e]; r1 = sE[w][e + 1]; r2 = sE[w][e + 2]; }
        float t0 = r0 + 1e-8f, t1 = r1 + 1e-8f, t2 = r2 + 1e-8f;
        float ang = sqrtf(t0 * t0 + t1 * t1 + t2 * t2);
        float inv = 1.0f / ang;
        float x = r0 * inv, y = r1 * inv, z = r2 * inv;
        float s, c;
        sincosf(ang, &s, &c);
        float ic = 1.0f - c;
        float R[9];
        R[0] = 1.0f - ic * (y * y + z * z);
        R[1] = -s * z + ic * x * y;
        R[2] =  s * y + ic * x * z;
        R[3] =  s * z + ic * x * y;
        R[4] = 1.0f - ic * (x * x + z * z);
        R[5] = -s * x + ic * y * z;
        R[6] = -s * y + ic * x * z;
        R[7] =  s * x + ic * y * z;
        R[8] = 1.0f - ic * (x * x + y * y);
        #pragma unroll
        for (int m = 0; m < 9; m++) sR[w][lane][m] = R[m];
        if (lane >= 1) {
            int s0 = 11 + (lane - 1) * 9;
            #pragma unroll
            for (int m = 0; m < 9; m++)
                write_hl(xrow, s0 + m, R[m] - ((m == 0 || m == 4 || m == 8) ? 1.0f : 0.0f));
        }
    }
    if (lane == 0)  write_hl(xrow, 0, 1.0f);
    if (lane < 10)  write_hl(xrow, 1 + lane, beta[b * 10 + lane]);

    if (lane < 16) {
        float jx = g_J0[lane * 3 + 0], jy = g_J0[lane * 3 + 1], jz = g_J0[lane * 3 + 2];
        #pragma unroll
        for (int s = 0; s < 10; s++) {
            float bs = beta[b * 10 + s];
            jx = fmaf(bs, g_Js[s * 48 + lane * 3 + 0], jx);
            jy = fmaf(bs, g_Js[s * 48 + lane * 3 + 1], jy);
            jz = fmaf(bs, g_Js[s * 48 + lane * 3 + 2], jz);
        }
        sJ[w][lane][0] = jx; sJ[w][lane][1] = jy; sJ[w][lane][2] = jz;
    }
    __syncwarp();

    if (lane == 0) {
        #pragma unroll
        for (int c = 0; c < 3; c++) {
            #pragma unroll
            for (int d = 0; d < 3; d++) sG[w][0][c * 4 + d] = sR[w][0][c * 3 + d];
            sG[w][0][c * 4 + 3] = sJ[w][0][c];
        }
    }
    __syncwarp();

    if (lane < 5) {
        float pr[9], pt[3];
        #pragma unroll
        for (int c = 0; c < 3; c++) {
            #pragma unroll
            for (int d = 0; d < 3; d++) pr[c * 3 + d] = sG[w][0][c * 4 + d];
            pt[c] = sG[w][0][c * 4 + 3];
        }
        int p = 0;
        #pragma unroll
        for (int st = 0; st < 3; st++) {
            int j = 1 + lane * 3 + st;
            float rj[9];
            #pragma unroll
            for (int m = 0; m < 9; m++) rj[m] = sR[w][j][m];
            float nr[9], nt[3];
            #pragma unroll
            for (int c = 0; c < 3; c++)
                #pragma unroll
                for (int d = 0; d < 3; d++)
                    nr[c * 3 + d] = pr[c * 3 + 0] * rj[0 * 3 + d]
                                  + pr[c * 3 + 1] * rj[1 * 3 + d]
                                  + pr[c * 3 + 2] * rj[2 * 3 + d];
            float dx = sJ[w][j][0] - sJ[w][p][0];
            float dy = sJ[w][j][1] - sJ[w][p][1];
            float dz = sJ[w][j][2] - sJ[w][p][2];
            #pragma unroll
            for (int c = 0; c < 3; c++)
                nt[c] = pr[c * 3 + 0] * dx + pr[c * 3 + 1] * dy + pr[c * 3 + 2] * dz + pt[c];
            #pragma unroll
            for (int c = 0; c < 3; c++) {
                #pragma unroll
                for (int d = 0; d < 3; d++) sG[w][j][c * 4 + d] = nr[c * 3 + d];
                sG[w][j][c * 4 + 3] = nt[c];
            }
            #pragma unroll
            for (int m = 0; m < 9; m++) pr[m] = nr[m];
            pt[0] = nt[0]; pt[1] = nt[1]; pt[2] = nt[2];
            p = j;
        }
    }
    __syncwarp();

    if (lane < 16) {
        float jx = sJ[w][lane][0], jy = sJ[w][lane][1], jz = sJ[w][lane][2];
        #pragma unroll
        for (int c = 0; c < 3; c++) {
            float a0 = sG[w][lane][c * 4 + 0];
            float a1 = sG[w][lane][c * 4 + 1];
            float a2 = sG[w][lane][c * 4 + 2];
            float at = sG[w][lane][c * 4 + 3] - (a0 * jx + a1 * jy + a2 * jz);
            int base = b * 192 + lane * 12 + c * 4;
            g_A[base + 0] = a0; g_A[base + 1] = a1;
            g_A[base + 2] = a2; g_A[base + 3] = at;
        }
    }
}

// =====================================================================
// Kernel 3: bf16 mma.sync GEMM  M[8192,1024] = Xh[8192,480] * Cb[480,1024]
// CTA tile 128x128, BK=32, 3-stage cp.async pipeline, warp tile 64x32.
// =====================================================================
__global__ __launch_bounds__(256) void mma_kernel()
{
    __shared__ __align__(128) __nv_bfloat16 smA[3][128 * BKC];   // [st][m][k] 64B rows
    __shared__ __align__(128) __nv_bfloat16 smB[3][BKC * 128];   // [st][k][n] 256B rows

    const int tid = threadIdx.x;
    const int wid = tid >> 5, lane = tid & 31;
    const int bn0 = blockIdx.x * 128;
    const int bm0 = blockIdx.y * 128;
    const int warp_m = (wid & 1) * 64;
    const int warp_n = (wid >> 1) * 32;

    const uint32_t smA_u = (uint32_t)__cvta_generic_to_shared(&smA[0][0]);
    const uint32_t smB_u = (uint32_t)__cvta_generic_to_shared(&smB[0][0]);

    float acc[4][4][4];
    #pragma unroll
    for (int mt = 0; mt < 4; mt++)
        #pragma unroll
        for (int nt = 0; nt < 4; nt++)
            #pragma unroll
            for (int q = 0; q < 4; q++) acc[mt][nt][q] = 0.f;

    auto load_chunk = [&](int kc, int st) {
        #pragma unroll
        for (int i = 0; i < 2; i++) {
            int idx = i * 256 + tid;
            int row = idx >> 2, c16 = idx & 3;
            uint32_t off = SWA((uint32_t)(row * 64 + c16 * 16));
            cp16(smA_u + st * 8192 + off,
                 g_Xh + (size_t)(bm0 + row) * KC + kc * BKC + c16 * 8);
        }
        #pragma unroll
        for (int i = 0; i < 2; i++) {
            int idx = i * 256 + tid;
            int row = idx >> 4, c16 = idx & 15;
            uint32_t off = SWB((uint32_t)(row * 256 + c16 * 16));
            cp16(smB_u + st * 8192 + off,
                 g_Cb + (size_t)(kc * BKC + row) * NP + bn0 + c16 * 8);
        }
    };

    load_chunk(0, 0); CP_COMMIT();
    load_chunk(1, 1); CP_COMMIT();

    const int r15 = lane & 15;
    const int kq  = lane >> 4;

    #pragma unroll 1
    for (int kc = 0; kc < NCH; kc++) {
        CP_WAIT1();
        __syncthreads();
        int nk = kc + 2;
        if (nk < NCH) load_chunk(nk, nk % 3);
        CP_COMMIT();

        int st = kc % 3;
        #pragma unroll
        for (int ks = 0; ks < 2; ks++) {
            uint32_t a[4][4], b[4][2];
            #pragma unroll
            for (int mt = 0; mt < 4; mt++) {
                uint32_t off = (uint32_t)((warp_m + mt * 16 + r15) * 64
                                          + (ks * 16 + kq * 8) * 2);
                ldsm_x4(a[mt], smA_u + st * 8192 + SWA(off));
            }
            #pragma unroll
            for (int nt = 0; nt < 4; nt++) {
                uint32_t off = (uint32_t)((ks * 16 + r15) * 256
                                          + (warp_n + nt * 8) * 2);
                ldsm_x2_t(b[nt], smB_u + st * 8192 + SWB(off));
            }
            #pragma unroll
            for (int mt = 0; mt < 4; mt++)
                #pragma unroll
                for (int nt = 0; nt < 4; nt++)
                    mma16816(acc[mt][nt], a[mt], b[nt]);
        }
    }

    // epilogue: lane l owns rows (l>>2, +8), cols (l&3)*2 within each 16x8 tile
    #pragma unroll
    for (int mt = 0; mt < 4; mt++) {
        #pragma unroll
        for (int nt = 0; nt < 4; nt++) {
            int r0 = bm0 + warp_m + mt * 16 + (lane >> 2);
            int c  = bn0 + warp_n + nt * 8 + (lane & 3) * 2;
            float2 v0 = make_float2(acc[mt][nt][0], acc[mt][nt][1]);
            float2 v1 = make_float2(acc[mt][nt][2], acc[mt][nt][3]);
            *(float2*)&g_M[(size_t)r0 * NP + c] = v0;
            *(float2*)&g_M[(size_t)(r0 + 8) * NP + c] = v1;
        }
    }
}

// =====================================================================
// Kernel 4: joints[b,k,c] = sum_j ( A[b,j,c,:3].M[b,j,k,:] + A[b,j,c,3]*W[k,j] )
// Block = 256 thr = 4 batches x 2 warps (j split 8+8); M staged coalesced;
// halved serial chains + 8 CTAs/SM for latency hiding.
// =====================================================================
__global__ __launch_bounds__(256) void reduce_kernel(float* __restrict__ out)
{
    __shared__ float Msh[4][1008];
    __shared__ float Ash[4][192];
    __shared__ float Wsh[336];
    __shared__ float Psh[4][2][64];

    int tid = threadIdx.x;
    int w = tid >> 5, lane = tid & 31;
    int bb = w >> 1;            // batch slot 0..3
    int jh = w & 1;             // j half
    int b0 = blockIdx.x * 4;

    for (int i = tid; i < 336; i += 256) Wsh[i] = g_W[i];
    // M rows: 4 batches x 252 float4, coalesced per row
    for (int i = tid; i < 4 * 252; i += 256) {
        int bt = i / 252, q = i % 252;
        ((float4*)&Msh[bt][0])[q] = *(const float4*)&g_M[(size_t)(b0 + bt) * NP + q * 4];
    }
    // A: 4 batches x 48 float4 (contiguous in g_A)
    for (int i = tid; i < 4 * 48; i += 256)
        ((float4*)&Ash[0][0])[i] = ((const float4*)&g_A[(size_t)b0 * 192])[i];
    __syncthreads();

    int j0 = jh * 8;
    #pragma unroll
    for (int rep = 0; rep < 2; rep++) {
        int o = lane + rep * 32;
        if (o < 63) {
            int k = o / 3, c = o % 3;
            float acc = 0.f;
            #pragma unroll
            for (int jj = 0; jj < 8; jj++) {
                int j = j0 + jj;
                const float* a = &Ash[bb][j * 12 + c * 4];
                const float* m = &Msh[bb][j * 63 + k * 3];
                acc = fmaf(a[0], m[0], acc);
                acc = fmaf(a[1], m[1], acc);
                acc = fmaf(a[2], m[2], acc);
                acc = fmaf(a[3], Wsh[k * 16 + j], acc);
            }
            Psh[bb][jh][o] = acc;
        }
    }
    __syncthreads();

    for (int i = tid; i < 4 * 63; i += 256) {
        int bt = i / 63, oo = i % 63;
        out[(size_t)(b0 + bt) * 63 + oo] = Psh[bt][0][oo] + Psh[bt][1][oo];
    }
}

// =====================================================================
extern "C" void kernel_launch(void* const* d_in, const int* in_sizes, int n_in,
                              void* d_out, int out_size)
{
    const float* beta  = (const float*)d_in[0];
    const float* theta = (const float*)d_in[1];
    const float* wrist = (const float*)d_in[2];
    const float* vt    = (const float*)d_in[3];
    const float* sd    = (const float*)d_in[4];
    const float* pd    = (const float*)d_in[5];
    const float* Jr    = (const float*)d_in[6];
    const float* hc    = (const float*)d_in[7];
    const float* hm    = (const float*)d_in[8];
    const float* wts   = (const float*)d_in[9];
    float* out = (float*)d_out;

    precomp_part<<<146 * NVS + 72, 384>>>(vt, sd, pd, Jr, wts);
    fk_kernel<<<1216, 256>>>(beta, theta, wrist, hc, hm);
    mma_kernel<<<dim3(NP / 128, NB / 128), 256>>>();
    reduce_kernel<<<2048, 256>>>(out);
}

// round 9
// speedup vs baseline: 2.0312x; 1.0647x over previous
#include <cuda_runtime.h>
#include <cuda_bf16.h>
#include <math.h>
#include <stdint.h>

// Problem constants
#define NB   8192          // batch
#define NV   778           // vertices
#define KC   512           // padded K stride (3x160 split: [Xhi|Xlo|Xhi] vs [Chi|Chi|Clo])
#define NP   1024          // padded N
#define BKC  32            // k per pipeline chunk
#define NCH  15            // 480 / 32 used chunks
#define NVS  8             // vertex splits for precomp_C
#define VPB  98            // verts per split block
#define RB   8             // batches per reduce CTA

// ---------------- scratch (device globals; zero-initialized at load) ----------------
__device__ __nv_bfloat16 g_Xh[(size_t)NB * KC];   // [b][k]  A operand bf16
__device__ __nv_bfloat16 g_Cb[(size_t)KC * NP];   // [k][o]  B operand bf16
__device__ float  g_Cp[NVS * 146 * 1008];         // fp32 partials of C
__device__ float  g_A[NB * 192];                  // [b][j][3x4]
__device__ float  g_M[(size_t)NB * NP];           // GEMM output [b][o]
__device__ float  g_Js[480];
__device__ float  g_J0[48];
__device__ float  g_W[336];

// ---------------- helpers ----------------
__device__ __forceinline__ __nv_bfloat16 hb(float x) { return __float2bfloat16(x); }
__device__ __forceinline__ __nv_bfloat16 lb(float x) {
    return __float2bfloat16(x - __bfloat162float(__float2bfloat16(x)));
}
__device__ __forceinline__ void ldsm_x4(uint32_t* r, uint32_t addr) {
    asm volatile("ldmatrix.sync.aligned.m8n8.x4.shared.b16 {%0,%1,%2,%3}, [%4];"
                 : "=r"(r[0]), "=r"(r[1]), "=r"(r[2]), "=r"(r[3]) : "r"(addr));
}
__device__ __forceinline__ void ldsm_x2_t(uint32_t* r, uint32_t addr) {
    asm volatile("ldmatrix.sync.aligned.m8n8.x2.trans.shared.b16 {%0,%1}, [%2];"
                 : "=r"(r[0]), "=r"(r[1]) : "r"(addr));
}
__device__ __forceinline__ void mma16816(float* d, const uint32_t* a, const uint32_t* b) {
    asm volatile("mma.sync.aligned.m16n8k16.row.col.f32.bf16.bf16.f32 "
                 "{%0,%1,%2,%3}, {%4,%5,%6,%7}, {%8,%9}, {%0,%1,%2,%3};"
                 : "+f"(d[0]), "+f"(d[1]), "+f"(d[2]), "+f"(d[3])
                 : "r"(a[0]), "r"(a[1]), "r"(a[2]), "r"(a[3]), "r"(b[0]), "r"(b[1]));
}
__device__ __forceinline__ void cp16(uint32_t saddr, const void* g) {
    asm volatile("cp.async.cg.shared.global [%0], [%1], 16;" :: "r"(saddr), "l"(g) : "memory");
}
#define CP_COMMIT() asm volatile("cp.async.commit_group;" ::: "memory")
#define CP_WAIT1()  asm volatile("cp.async.wait_group 1;" ::: "memory")
// A staging: 64B rows (32 halfs), swizzle bits[5:4] ^= bits[7:6]
#define SWA(o) ((o) ^ (((o) >> 2) & 0x30))
// B staging: 256B rows (128 halfs), swizzle bits[6:4] ^= bits[10:8]
#define SWB(o) ((o) ^ (((o) >> 4) & 0x70))

// =====================================================================
// Kernel 1: precomp_part — blocks 0..1167: C partials over 8 vertex splits;
//           blocks 1168..1239: small reductions (Js, J0, W).
// =====================================================================
__global__ __launch_bounds__(384) void precomp_part(
    const float* __restrict__ vt, const float* __restrict__ sd,
    const float* __restrict__ pd, const float* __restrict__ Jr,
    const float* __restrict__ wts)
{
    __shared__ float sB[64 * 3];
    __shared__ float sW[64 * 16];
    __shared__ float sJr[64 * 21];

    int t = threadIdx.x;
    int bid = blockIdx.x;

    if (bid < 146 * NVS) {
        int f  = bid >> 3;
        int vs = bid & 7;
        const float* brow = (f == 0) ? vt : ((f <= 10) ? (sd + (f - 1) * 2334)
                                                       : (pd + (f - 11) * 2334));
        int vstart = vs * VPB;
        int vend   = min(NV, vstart + VPB);
        int j = t / 21, k = t % 21;
        bool active = (t < 336);
        float a0 = 0.f, a1 = 0.f, a2 = 0.f;

        for (int v0 = vstart; v0 < vend; v0 += 64) {
            int nv = min(64, vend - v0);
            for (int i = t; i < nv * 3;  i += 384) sB[i]  = brow[v0 * 3 + i];
            for (int i = t; i < nv * 16; i += 384) sW[i]  = wts[v0 * 16 + i];
            for (int i = t; i < nv * 21; i += 384) sJr[i] = Jr[v0 * 21 + i];
            __syncthreads();
            if (active) {
                #pragma unroll 2
                for (int v = 0; v < nv; v++) {
                    float p = sW[v * 16 + j] * sJr[v * 21 + k];
                    a0 = fmaf(p, sB[v * 3 + 0], a0);
                    a1 = fmaf(p, sB[v * 3 + 1], a1);
                    a2 = fmaf(p, sB[v * 3 + 2], a2);
                }
            }
            __syncthreads();
        }
        if (active) {
            float* dst = g_Cp + ((size_t)vs * 146 + f) * 1008 + t * 3;
            dst[0] = a0; dst[1] = a1; dst[2] = a2;
        }
    } else {
        int gw   = (bid - 146 * NVS) * 12 + (t >> 5);    // 0..863
        int lane = t & 31;
        float acc = 0.f;
        if (gw < 480) {                 // Js[s][j][c]
            int s = gw / 48, r = gw % 48, j = r / 3, c = r % 3;
            for (int v = lane; v < NV; v += 32)
                acc = fmaf(Jr[v * 21 + j], sd[s * 2334 + v * 3 + c], acc);
        } else if (gw < 528) {          // J0[j][c]
            int idx = gw - 480, j = idx / 3, c = idx % 3;
            for (int v = lane; v < NV; v += 32)
                acc = fmaf(Jr[v * 21 + j], vt[v * 3 + c], acc);
        } else {                        // W[k][j]
            int idx = gw - 528, k = idx / 16, j = idx % 16;
            for (int v = lane; v < NV; v += 32)
                acc = fmaf(Jr[v * 21 + k], wts[v * 16 + j], acc);
        }
        #pragma unroll
        for (int off = 16; off > 0; off >>= 1)
            acc += __shfl_down_sync(0xffffffffu, acc, off);
        if (lane == 0) {
            if (gw < 480)      g_Js[gw] = acc;
            else if (gw < 528) g_J0[gw - 480] = acc;
            else               g_W[gw - 528] = acc;
        }
    }
}

// =====================================================================
// Kernel 2: fk_kernel — blocks 0..1023: per-batch forward kinematics
//           (one warp per batch -> g_Xh, g_A), coalesced smem-staged stores;
//           blocks 1024..1215: combine C partials -> bf16 hi/lo g_Cb.
// =====================================================================
__global__ __launch_bounds__(256) void fk_kernel(
    const float* __restrict__ beta, const float* __restrict__ theta,
    const float* __restrict__ wrist, const float* __restrict__ hc,
    const float* __restrict__ hm)
{
    if (blockIdx.x >= 1024) {
        // ---- combine C partials ----
        int idx = (blockIdx.x - 1024) * 256 + threadIdx.x;   // (f, o336)
        if (idx >= 146 * 336) return;
        int f = idx / 336, o = idx % 336;
        #pragma unroll
        for (int c = 0; c < 3; c++) {
            int o3 = o * 3 + c;
            float v = 0.f;
            #pragma unroll
            for (int vs = 0; vs < NVS; vs++)
                v += g_Cp[((size_t)vs * 146 + f) * 1008 + o3];
            g_Cb[(size_t)f * NP + o3]         = hb(v);
            g_Cb[(size_t)(160 + f) * NP + o3] = hb(v);
            g_Cb[(size_t)(320 + f) * NP + o3] = lb(v);
        }
        return;
    }

    __shared__ float sE[8][48];
    __shared__ float sR[8][16][9];
    __shared__ float sJ[8][16][3];
    __shared__ float sG[8][16][12];
    __shared__ float sX[8][160];
    __shared__ float sA[8][192];

    int w = threadIdx.x >> 5, lane = threadIdx.x & 31;
    int b = blockIdx.x * 8 + w;

    // zero X row (incl. pads 146..159)
    for (int e = lane; e < 160; e += 32) sX[w][e] = 0.f;

    for (int e = lane; e < 45; e += 32) {
        float v = hm[e];
        #pragma unroll
        for (int s = 0; s < 10; s++)
            v = fmaf(theta[b * 10 + s], hc[s * 45 + e], v);
        sE[w][e] = v;
    }
    __syncwarp();

    if (lane < 16) {
        float r0, r1, r2;
        if (lane == 0) { r0 = wrist[b * 3]; r1 = wrist[b * 3 + 1]; r2 = wrist[b * 3 + 2]; }
        else { int e = (lane - 1) * 3; r0 = sE[w][e]; r1 = sE[w][e + 1]; r2 = sE[w][e + 2]; }
        float t0 = r0 + 1e-8f, t1 = r1 + 1e-8f, t2 = r2 + 1e-8f;
        float ang = sqrtf(t0 * t0 + t1 * t1 + t2 * t2);
        float inv = 1.0f / ang;
        float x = r0 * inv, y = r1 * inv, z = r2 * inv;
        float s, c;
        sincosf(ang, &s, &c);
        float ic = 1.0f - c;
        float R[9];
        R[0] = 1.0f - ic * (y * y + z * z);
        R[1] = -s * z + ic * x * y;
        R[2] =  s * y + ic * x * z;
        R[3] =  s * z + ic * x * y;
        R[4] = 1.0f - ic * (x * x + z * z);
        R[5] = -s * x + ic * y * z;
        R[6] = -s * y + ic * x * z;
        R[7] =  s * x + ic * y * z;
        R[8] = 1.0f - ic * (x * x + y * y);
        #pragma unroll
        for (int m = 0; m < 9; m++) sR[w][lane][m] = R[m];
        if (lane >= 1) {
            int s0 = 11 + (lane - 1) * 9;
            #pragma unroll
            for (int m = 0; m < 9; m++)
                sX[w][s0 + m] = R[m] - ((m == 0 || m == 4 || m == 8) ? 1.0f : 0.0f);
        }
    }
    if (lane == 0)  sX[w][0] = 1.0f;
    if (lane < 10)  sX[w][1 + lane] = beta[b * 10 + lane];

    if (lane < 16) {
        float jx = g_J0[lane * 3 + 0], jy = g_J0[lane * 3 + 1], jz = g_J0[lane * 3 + 2];
        #pragma unroll
        for (int s = 0; s < 10; s++) {
            float bs = beta[b * 10 + s];
            jx = fmaf(bs, g_Js[s * 48 + lane * 3 + 0], jx);
            jy = fmaf(bs, g_Js[s * 48 + lane * 3 + 1], jy);
            jz = fmaf(bs, g_Js[s * 48 + lane * 3 + 2], jz);
        }
        sJ[w][lane][0] = jx; sJ[w][lane][1] = jy; sJ[w][lane][2] = jz;
    }
    __syncwarp();

    if (lane == 0) {
        #pragma unroll
        for (int c = 0; c < 3; c++) {
            #pragma unroll
            for (int d = 0; d < 3; d++) sG[w][0][c * 4 + d] = sR[w][0][c * 3 + d];
            sG[w][0][c * 4 + 3] = sJ[w][0][c];
        }
    }
    __syncwarp();

    if (lane < 5) {
        float pr[9], pt[3];
        #pragma unroll
        for (int c = 0; c < 3; c++) {
            #pragma unroll
            for (int d = 0; d < 3; d++) pr[c * 3 + d] = sG[w][0][c * 4 + d];
            pt[c] = sG[w][0][c * 4 + 3];
        }
        int p = 0;
        #pragma unroll
        for (int st = 0; st < 3; st++) {
            int j = 1 + lane * 3 + st;
            float rj[9];
            #pragma unroll
            for (int m = 0; m < 9; m++) rj[m] = sR[w][j][m];
            float nr[9], nt[3];
            #pragma unroll
            for (int c = 0; c < 3; c++)
                #pragma unroll
                for (int d = 0; d < 3; d++)
                    nr[c * 3 + d] = pr[c * 3 + 0] * rj[0 * 3 + d]
                                  + pr[c * 3 + 1] * rj[1 * 3 + d]
                                  + pr[c * 3 + 2] * rj[2 * 3 + d];
            float dx = sJ[w][j][0] - sJ[w][p][0];
            float dy = sJ[w][j][1] - sJ[w][p][1];
            float dz = sJ[w][j][2] - sJ[w][p][2];
            #pragma unroll
            for (int c = 0; c < 3; c++)
                nt[c] = pr[c * 3 + 0] * dx + pr[c * 3 + 1] * dy + pr[c * 3 + 2] * dz + pt[c];
            #pragma unroll
            for (int c = 0; c < 3; c++) {
                #pragma unroll
                for (int d = 0; d < 3; d++) sG[w][j][c * 4 + d] = nr[c * 3 + d];
                sG[w][j][c * 4 + 3] = nt[c];
            }
            #pragma unroll
            for (int m = 0; m < 9; m++) pr[m] = nr[m];
            pt[0] = nt[0]; pt[1] = nt[1]; pt[2] = nt[2];
            p = j;
        }
    }
    __syncwarp();

    if (lane < 16) {
        float jx = sJ[w][lane][0], jy = sJ[w][lane][1], jz = sJ[w][lane][2];
        #pragma unroll
        for (int c = 0; c < 3; c++) {
            float a0 = sG[w][lane][c * 4 + 0];
            float a1 = sG[w][lane][c * 4 + 1];
            float a2 = sG[w][lane][c * 4 + 2];
            float at = sG[w][lane][c * 4 + 3] - (a0 * jx + a1 * jy + a2 * jz);
            int base = lane * 12 + c * 4;
            sA[w][base + 0] = a0; sA[w][base + 1] = a1;
            sA[w][base + 2] = a2; sA[w][base + 3] = at;
        }
    }
    __syncwarp();

    // ---- coalesced global stores ----
    // X row: 512 bf16 = 256 b32, pattern [hi(0..159) | lo(0..159) | hi(0..159) | 0 x32]
    {
        __nv_bfloat162* xr2 = (__nv_bfloat162*)(g_Xh + (size_t)b * KC);
        for (int i = lane; i < 256; i += 32) {
            int p0 = 2 * i, p1 = p0 + 1;
            __nv_bfloat16 v0, v1;
            v0 = (p0 < 160) ? hb(sX[w][p0])
               : (p0 < 320) ? lb(sX[w][p0 - 160])
               : (p0 < 480) ? hb(sX[w][p0 - 320]) : hb(0.f);
            v1 = (p1 < 160) ? hb(sX[w][p1])
               : (p1 < 320) ? lb(sX[w][p1 - 160])
               : (p1 < 480) ? hb(sX[w][p1 - 320]) : hb(0.f);
            xr2[i] = __nv_bfloat162(v0, v1);
        }
    }
    // A row: 48 float4
    {
        float4* ar = (float4*)(g_A + (size_t)b * 192);
        const float4* sa = (const float4*)&sA[w][0];
        for (int i = lane; i < 48; i += 32) ar[i] = sa[i];
    }
}

// =====================================================================
// Kernel 3: bf16 mma.sync GEMM  M[8192,1024] = Xh[8192,480] * Cb[480,1024]
// CTA tile 128x128, BK=32, 3-stage cp.async pipeline, warp tile 64x32.
// =====================================================================
__global__ __launch_bounds__(256) void mma_kernel()
{
    __shared__ __align__(128) __nv_bfloat16 smA[3][128 * BKC];   // [st][m][k] 64B rows
    __shared__ __align__(128) __nv_bfloat16 smB[3][BKC * 128];   // [st][k][n] 256B rows

    const int tid = threadIdx.x;
    const int wid = tid >> 5, lane = tid & 31;
    const int bn0 = blockIdx.x * 128;
    const int bm0 = blockIdx.y * 128;
    const int warp_m = (wid & 1) * 64;
    const int warp_n = (wid >> 1) * 32;

    const uint32_t smA_u = (uint32_t)__cvta_generic_to_shared(&smA[0][0]);
    const uint32_t smB_u = (uint32_t)__cvta_generic_to_shared(&smB[0][0]);

    float acc[4][4][4];
    #pragma unroll
    for (int mt = 0; mt < 4; mt++)
        #pragma unroll
        for (int nt = 0; nt < 4; nt++)
            #pragma unroll
            for (int q = 0; q < 4; q++) acc[mt][nt][q] = 0.f;

    auto load_chunk = [&](int kc, int st) {
        #pragma unroll
        for (int i = 0; i < 2; i++) {
            int idx = i * 256 + tid;
            int row = idx >> 2, c16 = idx & 3;
            uint32_t off = SWA((uint32_t)(row * 64 + c16 * 16));
            cp16(smA_u + st * 8192 + off,
                 g_Xh + (size_t)(bm0 + row) * KC + kc * BKC + c16 * 8);
        }
        #pragma unroll
        for (int i = 0; i < 2; i++) {
            int idx = i * 256 + tid;
            int row = idx >> 4, c16 = idx & 15;
            uint32_t off = SWB((uint32_t)(row * 256 + c16 * 16));
            cp16(smB_u + st * 8192 + off,
                 g_Cb + (size_t)(kc * BKC + row) * NP + bn0 + c16 * 8);
        }
    };

    load_chunk(0, 0); CP_COMMIT();
    load_chunk(1, 1); CP_COMMIT();

    const int r15 = lane & 15;
    const int kq  = lane >> 4;

    #pragma unroll 1
    for (int kc = 0; kc < NCH; kc++) {
        CP_WAIT1();
        __syncthreads();
        int nk = kc + 2;
        if (nk < NCH) load_chunk(nk, nk % 3);
        CP_COMMIT();

        int st = kc % 3;
        #pragma unroll
        for (int ks = 0; ks < 2; ks++) {
            uint32_t a[4][4], b[4][2];
            #pragma unroll
            for (int mt = 0; mt < 4; mt++) {
                uint32_t off = (uint32_t)((warp_m + mt * 16 + r15) * 64
                                          + (ks * 16 + kq * 8) * 2);
                ldsm_x4(a[mt], smA_u + st * 8192 + SWA(off));
            }
            #pragma unroll
            for (int nt = 0; nt < 4; nt++) {
                uint32_t off = (uint32_t)((ks * 16 + r15) * 256
                                          + (warp_n + nt * 8) * 2);
                ldsm_x2_t(b[nt], smB_u + st * 8192 + SWB(off));
            }
            #pragma unroll
            for (int mt = 0; mt < 4; mt++)
                #pragma unroll
                for (int nt = 0; nt < 4; nt++)
                    mma16816(acc[mt][nt], a[mt], b[nt]);
        }
    }

    // epilogue: lane l owns rows (l>>2, +8), cols (l&3)*2 within each 16x8 tile
    #pragma unroll
    for (int mt = 0; mt < 4; mt++) {
        #pragma unroll
        for (int nt = 0; nt < 4; nt++) {
            int r0 = bm0 + warp_m + mt * 16 + (lane >> 2);
            int c  = bn0 + warp_n + nt * 8 + (lane & 3) * 2;
            float2 v0 = make_float2(acc[mt][nt][0], acc[mt][nt][1]);
            float2 v1 = make_float2(acc[mt][nt][2], acc[mt][nt][3]);
            *(float2*)&g_M[(size_t)r0 * NP + c] = v0;
            *(float2*)&g_M[(size_t)(r0 + 8) * NP + c] = v1;
        }
    }
}

// =====================================================================
// Kernel 4: joints[b,k,c] = sum_j ( A[b,j,c,:3].M[b,j,k,:] + A[b,j,c,3]*W[k,j] )
// Block = 512 thr = 8 batches x 2 warps (j split 8+8). All index math is
// shift/mask (padded strides); A read via LDS.128.
// =====================================================================
__global__ __launch_bounds__(512) void reduce_kernel(float* __restrict__ out)
{
    __shared__ float Msh[RB][1008];
    __shared__ float Ash[RB][192];
    __shared__ float Wsh[336];
    __shared__ float Psh[RB][2][64];

    int tid = threadIdx.x;
    int w = tid >> 5, lane = tid & 31;
    int bb = w >> 1;            // batch slot 0..7
    int jh = w & 1;             // j half
    int b0 = blockIdx.x * RB;

    if (tid < 336) Wsh[tid] = g_W[tid];
    // M rows: RB batches x 252 float4 (padded loop stride 256, shift/mask idx)
    #pragma unroll
    for (int i = tid; i < RB * 256; i += 512) {
        int bt = i >> 8, q = i & 255;
        if (q < 252)
            ((float4*)&Msh[bt][0])[q] = *(const float4*)&g_M[(size_t)(b0 + bt) * NP + q * 4];
    }
    // A: RB batches x 48 float4 (contiguous; padded to 64/batch)
    #pragma unroll
    for (int i = tid; i < RB * 64; i += 512) {
        int bt = i >> 6, q = i & 63;
        if (q < 48)
            ((float4*)&Ash[bt][0])[q] = ((const float4*)&g_A[(size_t)b0 * 192])[bt * 48 + q];
    }
    __syncthreads();

    int j0 = jh * 8;
    #pragma unroll
    for (int rep = 0; rep < 2; rep++) {
        int o = lane + rep * 32;
        if (o < 63) {
            int k = (o * 0x5556) >> 16;      // o/3 for o<63
            int c = o - k * 3;
            float acc = 0.f;
            const float4* af = (const float4*)&Ash[bb][0];
            #pragma unroll
            for (int jj = 0; jj < 8; jj++) {
                int j = j0 + jj;
                float4 a = af[j * 3 + c];
                const float* m = &Msh[bb][j * 63 + o];   // j*63 + k*3 + d base (d=0 at o-c)
                const float* mb = &Msh[bb][j * 63 + k * 3];
                acc = fmaf(a.x, mb[0], acc);
                acc = fmaf(a.y, mb[1], acc);
                acc = fmaf(a.z, mb[2], acc);
                acc = fmaf(a.w, Wsh[k * 16 + j], acc);
                (void)m;
            }
            Psh[bb][jh][o] = acc;
        }
    }
    __syncthreads();

    #pragma unroll
    for (int i = tid; i < RB * 64; i += 512) {
        int bt = i >> 6, oo = i & 63;
        if (oo < 63)
            out[(size_t)(b0 + bt) * 63 + oo] = Psh[bt][0][oo] + Psh[bt][1][oo];
    }
}

// =====================================================================
extern "C" void kernel_launch(void* const* d_in, const int* in_sizes, int n_in,
                              void* d_out, int out_size)
{
    const float* beta  = (const float*)d_in[0];
    const float* theta = (const float*)d_in[1];
    const float* wrist = (const float*)d_in[2];
    const float* vt    = (const float*)d_in[3];
    const float* sd    = (const float*)d_in[4];
    const float* pd    = (const float*)d_in[5];
    const float* Jr    = (const float*)d_in[6];
    const float* hc    = (const float*)d_in[7];
    const float* hm    = (const float*)d_in[8];
    const float* wts   = (const float*)d_in[9];
    float* out = (float*)d_out;

    precomp_part<<<146 * NVS + 72, 384>>>(vt, sd, pd, Jr, wts);
    fk_kernel<<<1216, 256>>>(beta, theta, wrist, hc, hm);
    mma_kernel<<<dim3(NP / 128, NB / 128), 256>>>();
    reduce_kernel<<<NB / RB, 512>>>(out);
}

// round 10
// speedup vs baseline: 2.0634x; 1.0159x over previous
#include <cuda_runtime.h>
#include <cuda_bf16.h>
#include <math.h>
#include <stdint.h>

// Problem constants
#define NB   8192          // batch
#define NV   778           // vertices
#define KC   512           // padded K stride (3x160 split: [Xhi|Xlo|Xhi] vs [Chi|Chi|Clo])
#define NP   1024          // padded N = 16 joints * 64 (63 used per joint)
#define BKC  32            // k per pipeline chunk
#define NCH  15            // 480 / 32 used chunks
#define NVS  8             // vertex splits for precomp_C
#define VPB  98            // verts per split block

// ---------------- scratch (device globals; zero-initialized at load) ----------------
__device__ __nv_bfloat16 g_Xh[(size_t)NB * KC];   // [b][k]  A operand bf16
__device__ __nv_bfloat16 g_Cb[(size_t)KC * NP];   // [k][j*64 + k21*3 + d]  B operand bf16
__device__ float  g_Cp[NVS * 146 * 1008];         // fp32 partials of C
__device__ float  g_A[NB * 192];                  // [b][j][3x4]
__device__ float  g_Js[480];
__device__ float  g_J0[48];
__device__ float  g_W[336];

// ---------------- helpers ----------------
__device__ __forceinline__ __nv_bfloat16 hb(float x) { return __float2bfloat16(x); }
__device__ __forceinline__ __nv_bfloat16 lb(float x) {
    return __float2bfloat16(x - __bfloat162float(__float2bfloat16(x)));
}
__device__ __forceinline__ void ldsm_x4(uint32_t* r, uint32_t addr) {
    asm volatile("ldmatrix.sync.aligned.m8n8.x4.shared.b16 {%0,%1,%2,%3}, [%4];"
                 : "=r"(r[0]), "=r"(r[1]), "=r"(r[2]), "=r"(r[3]) : "r"(addr));
}
__device__ __forceinline__ void ldsm_x2_t(uint32_t* r, uint32_t addr) {
    asm volatile("ldmatrix.sync.aligned.m8n8.x2.trans.shared.b16 {%0,%1}, [%2];"
                 : "=r"(r[0]), "=r"(r[1]) : "r"(addr));
}
__device__ __forceinline__ void mma16816(float* d, const uint32_t* a, const uint32_t* b) {
    asm volatile("mma.sync.aligned.m16n8k16.row.col.f32.bf16.bf16.f32 "
                 "{%0,%1,%2,%3}, {%4,%5,%6,%7}, {%8,%9}, {%0,%1,%2,%3};"
                 : "+f"(d[0]), "+f"(d[1]), "+f"(d[2]), "+f"(d[3])
                 : "r"(a[0]), "r"(a[1]), "r"(a[2]), "r"(a[3]), "r"(b[0]), "r"(b[1]));
}
__device__ __forceinline__ void cp16(uint32_t saddr, const void* g) {
    asm volatile("cp.async.cg.shared.global [%0], [%1], 16;" :: "r"(saddr), "l"(g) : "memory");
}
#define CP_COMMIT() asm volatile("cp.async.commit_group;" ::: "memory")
#define CP_WAIT1()  asm volatile("cp.async.wait_group 1;" ::: "memory")
#define CP_WAIT0()  asm volatile("cp.async.wait_group 0;" ::: "memory")
// A staging: 64B rows (32 halfs), swizzle bits[5:4] ^= bits[7:6]
#define SWA(o) ((o) ^ (((o) >> 2) & 0x30))
// B staging: 256B rows (128 halfs), swizzle bits[6:4] ^= bits[10:8]
#define SWB(o) ((o) ^ (((o) >> 4) & 0x70))

// =====================================================================
// Kernel 1: precomp_part — blocks 0..1167: C partials over 8 vertex splits;
//           blocks 1168..1239: small reductions (Js, J0, W).
// =====================================================================
__global__ __launch_bounds__(384) void precomp_part(
    const float* __restrict__ vt, const float* __restrict__ sd,
    const float* __restrict__ pd, const float* __restrict__ Jr,
    const float* __restrict__ wts)
{
    __shared__ float sB[64 * 3];
    __shared__ float sW[64 * 16];
    __shared__ float sJr[64 * 21];

    int t = threadIdx.x;
    int bid = blockIdx.x;

    if (bid < 146 * NVS) {
        int f  = bid >> 3;
        int vs = bid & 7;
        const float* brow = (f == 0) ? vt : ((f <= 10) ? (sd + (f - 1) * 2334)
                                                       : (pd + (f - 11) * 2334));
        int vstart = vs * VPB;
        int vend   = min(NV, vstart + VPB);
        int j = t / 21, k = t % 21;
        bool active = (t < 336);
        float a0 = 0.f, a1 = 0.f, a2 = 0.f;

        for (int v0 = vstart; v0 < vend; v0 += 64) {
            int nv = min(64, vend - v0);
            for (int i = t; i < nv * 3;  i += 384) sB[i]  = brow[v0 * 3 + i];
            for (int i = t; i < nv * 16; i += 384) sW[i]  = wts[v0 * 16 + i];
            for (int i = t; i < nv * 21; i += 384) sJr[i] = Jr[v0 * 21 + i];
            __syncthreads();
            if (active) {
                #pragma unroll 2
                for (int v = 0; v < nv; v++) {
                    float p = sW[v * 16 + j] * sJr[v * 21 + k];
                    a0 = fmaf(p, sB[v * 3 + 0], a0);
                    a1 = fmaf(p, sB[v * 3 + 1], a1);
                    a2 = fmaf(p, sB[v * 3 + 2], a2);
                }
            }
            __syncthreads();
        }
        if (active) {
            float* dst = g_Cp + ((size_t)vs * 146 + f) * 1008 + t * 3;
            dst[0] = a0; dst[1] = a1; dst[2] = a2;
        }
    } else {
        int gw   = (bid - 146 * NVS) * 12 + (t >> 5);    // 0..863
        int lane = t & 31;
        float acc = 0.f;
        if (gw < 480) {                 // Js[s][j][c]
            int s = gw / 48, r = gw % 48, j = r / 3, c = r % 3;
            for (int v = lane; v < NV; v += 32)
                acc = fmaf(Jr[v * 21 + j], sd[s * 2334 + v * 3 + c], acc);
        } else if (gw < 528) {          // J0[j][c]
            int idx = gw - 480, j = idx / 3, c = idx % 3;
            for (int v = lane; v < NV; v += 32)
                acc = fmaf(Jr[v * 21 + j], vt[v * 3 + c], acc);
        } else {                        // W[k][j]
            int idx = gw - 528, k = idx / 16, j = idx % 16;
            for (int v = lane; v < NV; v += 32)
                acc = fmaf(Jr[v * 21 + k], wts[v * 16 + j], acc);
        }
        #pragma unroll
        for (int off = 16; off > 0; off >>= 1)
            acc += __shfl_down_sync(0xffffffffu, acc, off);
        if (lane == 0) {
            if (gw < 480)      g_Js[gw] = acc;
            else if (gw < 528) g_J0[gw - 480] = acc;
            else               g_W[gw - 528] = acc;
        }
    }
}

// =====================================================================
// Kernel 2: fk_kernel — blocks 0..1023: per-batch FK (g_Xh, g_A) AND the
//           W-translation term written to out[b][*] (initializes out);
//           blocks 1024..1215: combine C partials -> bf16, padded-j layout.
// =====================================================================
__global__ __launch_bounds__(256) void fk_kernel(
    const float* __restrict__ beta, const float* __restrict__ theta,
    const float* __restrict__ wrist, const float* __restrict__ hc,
    const float* __restrict__ hm, float* __restrict__ out)
{
    if (blockIdx.x >= 1024) {
        // ---- combine C partials, write to column j*64 + k21*3 + c ----
        int idx = (blockIdx.x - 1024) * 256 + threadIdx.x;   // (f, o336)
        if (idx >= 146 * 336) return;
        int f = idx / 336, o = idx % 336;
        int j = o / 21, k21 = o % 21;
        int col = j * 64 + k21 * 3;
        #pragma unroll
        for (int c = 0; c < 3; c++) {
            int o3 = o * 3 + c;
            float v = 0.f;
            #pragma unroll
            for (int vs = 0; vs < NVS; vs++)
                v += g_Cp[((size_t)vs * 146 + f) * 1008 + o3];
            g_Cb[(size_t)f * NP + col + c]         = hb(v);
            g_Cb[(size_t)(160 + f) * NP + col + c] = hb(v);
            g_Cb[(size_t)(320 + f) * NP + col + c] = lb(v);
        }
        return;
    }

    __shared__ float sE[8][48];
    __shared__ float sR[8][16][9];
    __shared__ float sJ[8][16][3];
    __shared__ float sG[8][16][12];
    __shared__ float sX[8][160];
    __shared__ float sA[8][192];

    int w = threadIdx.x >> 5, lane = threadIdx.x & 31;
    int b = blockIdx.x * 8 + w;

    // zero X row (incl. pads 146..159)
    for (int e = lane; e < 160; e += 32) sX[w][e] = 0.f;

    for (int e = lane; e < 45; e += 32) {
        float v = hm[e];
        #pragma unroll
        for (int s = 0; s < 10; s++)
            v = fmaf(theta[b * 10 + s], hc[s * 45 + e], v);
        sE[w][e] = v;
    }
    __syncwarp();

    if (lane < 16) {
        float r0, r1, r2;
        if (lane == 0) { r0 = wrist[b * 3]; r1 = wrist[b * 3 + 1]; r2 = wrist[b * 3 + 2]; }
        else { int e = (lane - 1) * 3; r0 = sE[w][e]; r1 = sE[w][e + 1]; r2 = sE[w][e + 2]; }
        float t0 = r0 + 1e-8f, t1 = r1 + 1e-8f, t2 = r2 + 1e-8f;
        float ang = sqrtf(t0 * t0 + t1 * t1 + t2 * t2);
        float inv = 1.0f / ang;
        float x = r0 * inv, y = r1 * inv, z = r2 * inv;
        float s, c;
        sincosf(ang, &s, &c);
        float ic = 1.0f - c;
        float R[9];
        R[0] = 1.0f - ic * (y * y + z * z);
        R[1] = -s * z + ic * x * y;
        R[2] =  s * y + ic * x * z;
        R[3] =  s * z + ic * x * y;
        R[4] = 1.0f - ic * (x * x + z * z);
        R[5] = -s * x + ic * y * z;
        R[6] = -s * y + ic * x * z;
        R[7] =  s * x + ic * y * z;
        R[8] = 1.0f - ic * (x * x + y * y);
        #pragma unroll
        for (int m = 0; m < 9; m++) sR[w][lane][m] = R[m];
        if (lane >= 1) {
            int s0 = 11 + (lane - 1) * 9;
            #pragma unroll
            for (int m = 0; m < 9; m++)
                sX[w][s0 + m] = R[m] - ((m == 0 || m == 4 || m == 8) ? 1.0f : 0.0f);
        }
    }
    if (lane == 0)  sX[w][0] = 1.0f;
    if (lane < 10)  sX[w][1 + lane] = beta[b * 10 + lane];

    if (lane < 16) {
        float jx = g_J0[lane * 3 + 0], jy = g_J0[lane * 3 + 1], jz = g_J0[lane * 3 + 2];
        #pragma unroll
        for (int s = 0; s < 10; s++) {
            float bs = beta[b * 10 + s];
            jx = fmaf(bs, g_Js[s * 48 + lane * 3 + 0], jx);
            jy = fmaf(bs, g_Js[s * 48 + lane * 3 + 1], jy);
            jz = fmaf(bs, g_Js[s * 48 + lane * 3 + 2], jz);
        }
        sJ[w][lane][0] = jx; sJ[w][lane][1] = jy; sJ[w][lane][2] = jz;
    }
    __syncwarp();

    if (lane == 0) {
        #pragma unroll
        for (int c = 0; c < 3; c++) {
            #pragma unroll
            for (int d = 0; d < 3; d++) sG[w][0][c * 4 + d] = sR[w][0][c * 3 + d];
            sG[w][0][c * 4 + 3] = sJ[w][0][c];
        }
    }
    __syncwarp();

    if (lane < 5) {
        float pr[9], pt[3];
        #pragma unroll
        for (int c = 0; c < 3; c++) {
            #pragma unroll
            for (int d = 0; d < 3; d++) pr[c * 3 + d] = sG[w][0][c * 4 + d];
            pt[c] = sG[w][0][c * 4 + 3];
        }
        int p = 0;
        #pragma unroll
        for (int st = 0; st < 3; st++) {
            int j = 1 + lane * 3 + st;
            float rj[9];
            #pragma unroll
            for (int m = 0; m < 9; m++) rj[m] = sR[w][j][m];
            float nr[9], nt[3];
            #pragma unroll
            for (int c = 0; c < 3; c++)
                #pragma unroll
                for (int d = 0; d < 3; d++)
                    nr[c * 3 + d] = pr[c * 3 + 0] * rj[0 * 3 + d]
                                  + pr[c * 3 + 1] * rj[1 * 3 + d]
                                  + pr[c * 3 + 2] * rj[2 * 3 + d];
            float dx = sJ[w][j][0] - sJ[w][p][0];
            float dy = sJ[w][j][1] - sJ[w][p][1];
            float dz = sJ[w][j][2] - sJ[w][p][2];
            #pragma unroll
            for (int c = 0; c < 3; c++)
                nt[c] = pr[c * 3 + 0] * dx + pr[c * 3 + 1] * dy + pr[c * 3 + 2] * dz + pt[c];
            #pragma unroll
            for (int c = 0; c < 3; c++) {
                #pragma unroll
                for (int d = 0; d < 3; d++) sG[w][j][c * 4 + d] = nr[c * 3 + d];
                sG[w][j][c * 4 + 3] = nt[c];
            }
            #pragma unroll
            for (int m = 0; m < 9; m++) pr[m] = nr[m];
            pt[0] = nt[0]; pt[1] = nt[1]; pt[2] = nt[2];
            p = j;
        }
    }
    __syncwarp();

    if (lane < 16) {
        float jx = sJ[w][lane][0], jy = sJ[w][lane][1], jz = sJ[w][lane][2];
        #pragma unroll
        for (int c = 0; c < 3; c++) {
            float a0 = sG[w][lane][c * 4 + 0];
            float a1 = sG[w][lane][c * 4 + 1];
            float a2 = sG[w][lane][c * 4 + 2];
            float at = sG[w][lane][c * 4 + 3] - (a0 * jx + a1 * jy + a2 * jz);
            int base = lane * 12 + c * 4;
            sA[w][base + 0] = a0; sA[w][base + 1] = a1;
            sA[w][base + 2] = a2; sA[w][base + 3] = at;
        }
    }
    __syncwarp();

    // ---- coalesced global stores ----
    // X row: 512 bf16 = 256 b32, pattern [hi(0..159) | lo(0..159) | hi(0..159) | 0 x32]
    {
        __nv_bfloat162* xr2 = (__nv_bfloat162*)(g_Xh + (size_t)b * KC);
        for (int i = lane; i < 256; i += 32) {
            int p0 = 2 * i, p1 = p0 + 1;
            __nv_bfloat16 v0, v1;
            v0 = (p0 < 160) ? hb(sX[w][p0])
               : (p0 < 320) ? lb(sX[w][p0 - 160])
               : (p0 < 480) ? hb(sX[w][p0 - 320]) : hb(0.f);
            v1 = (p1 < 160) ? hb(sX[w][p1])
               : (p1 < 320) ? lb(sX[w][p1 - 160])
               : (p1 < 480) ? hb(sX[w][p1 - 320]) : hb(0.f);
            xr2[i] = __nv_bfloat162(v0, v1);
        }
    }
    // A row: 48 float4
    {
        float4* ar = (float4*)(g_A + (size_t)b * 192);
        const float4* sa = (const float4*)&sA[w][0];
        for (int i = lane; i < 48; i += 32) ar[i] = sa[i];
    }
    // W-translation term: out[b][k*3+c] = sum_j A[b][j][c*4+3] * W[k][j]
    // (initializes out; mma epilogue atomically adds the rotation part)
    for (int o = lane; o < 63; o += 32) {
        int k = (o * 21846) >> 16;      // o/3 for o < 63
        int c = o - k * 3;
        float acc = 0.f;
        #pragma unroll
        for (int j = 0; j < 16; j++)
            acc = fmaf(sA[w][j * 12 + c * 4 + 3], g_W[k * 16 + j], acc);
        out[(size_t)b * 63 + o] = acc;
    }
}

// =====================================================================
// Kernel 3: FUSED bf16 GEMM + joint reduction.
// GEMM tile 128x128 (bm=128 batches, bn=128 cols = 2 complete joints j0,j0+1).
// Epilogue: stage fp32 tile in smem (2 halves), contract with A[b, j0..j0+1],
// atomicAdd 63 partials per batch into out.  No g_M round-trip.
// =====================================================================
__global__ __launch_bounds__(256) void mma_fused(float* __restrict__ out)
{
    __shared__ __align__(128) char smem[49152];

    const int tid = threadIdx.x;
    const int wid = tid >> 5, lane = tid & 31;
    const int bn0 = blockIdx.x * 128;
    const int bm0 = blockIdx.y * 128;
    const int j0  = blockIdx.x * 2;          // first joint of this N tile
    const int warp_m = (wid & 1) * 64;
    const int warp_n = (wid >> 1) * 32;

    const uint32_t smA_u = (uint32_t)__cvta_generic_to_shared(smem);
    const uint32_t smB_u = smA_u + 24576;

    float acc[4][4][4];
    #pragma unroll
    for (int mt = 0; mt < 4; mt++)
        #pragma unroll
        for (int nt = 0; nt < 4; nt++)
            #pragma unroll
            for (int q = 0; q < 4; q++) acc[mt][nt][q] = 0.f;

    auto load_chunk = [&](int kc, int st) {
        #pragma unroll
        for (int i = 0; i < 2; i++) {
            int idx = i * 256 + tid;
            int row = idx >> 2, c16 = idx & 3;
            uint32_t off = SWA((uint32_t)(row * 64 + c16 * 16));
            cp16(smA_u + st * 8192 + off,
                 g_Xh + (size_t)(bm0 + row) * KC + kc * BKC + c16 * 8);
        }
        #pragma unroll
        for (int i = 0; i < 2; i++) {
            int idx = i * 256 + tid;
            int row = idx >> 4, c16 = idx & 15;
            uint32_t off = SWB((uint32_t)(row * 256 + c16 * 16));
            cp16(smB_u + st * 8192 + off,
                 g_Cb + (size_t)(kc * BKC + row) * NP + bn0 + c16 * 8);
        }
    };

    load_chunk(0, 0); CP_COMMIT();
    load_chunk(1, 1); CP_COMMIT();

    const int r15 = lane & 15;
    const int kq  = lane >> 4;

    #pragma unroll 1
    for (int kc = 0; kc < NCH; kc++) {
        CP_WAIT1();
        __syncthreads();
        int nk = kc + 2;
        if (nk < NCH) load_chunk(nk, nk % 3);
        CP_COMMIT();

        int st = kc % 3;
        #pragma unroll
        for (int ks = 0; ks < 2; ks++) {
            uint32_t a[4][4], b[4][2];
            #pragma unroll
            for (int mt = 0; mt < 4; mt++) {
                uint32_t off = (uint32_t)((warp_m + mt * 16 + r15) * 64
                                          + (ks * 16 + kq * 8) * 2);
                ldsm_x4(a[mt], smA_u + st * 8192 + SWA(off));
            }
            #pragma unroll
            for (int nt = 0; nt < 4; nt++) {
                uint32_t off = (uint32_t)((ks * 16 + r15) * 256
                                          + (warp_n + nt * 8) * 2);
                ldsm_x2_t(b[nt], smB_u + st * 8192 + SWB(off));
            }
            #pragma unroll
            for (int mt = 0; mt < 4; mt++)
                #pragma unroll
                for (int nt = 0; nt < 4; nt++)
                    mma16816(acc[mt][nt], a[mt], b[nt]);
        }
    }

    // ================= fused epilogue =================
    CP_WAIT0();
    __syncthreads();      // pipeline buffers dead; smem arena is free

    float* sA2 = (float*)smem;                 // [128 batches][24] = 12 KB
    float* sM  = (float*)(smem + 12288);       // [64 rows][132]    = 33 KB

    // load A slice for this CTA's 128 batches, joints j0, j0+1 (6 float4/batch)
    {
        const float4* gA4 = (const float4*)(g_A + (size_t)bm0 * 192);
        float4* sA4 = (float4*)sA2;
        #pragma unroll
        for (int i = tid; i < 768; i += 256) {
            int bl = i / 6, q = i - bl * 6;
            sA4[bl * 6 + q] = gA4[bl * 48 + j0 * 3 + q];
        }
    }

    #pragma unroll
    for (int h = 0; h < 2; h++) {
        // warps owning rows [h*64, h*64+64) store their accumulators
        if ((wid & 1) == h) {
            #pragma unroll
            for (int mt = 0; mt < 4; mt++) {
                int rl = mt * 16 + (lane >> 2);
                #pragma unroll
                for (int nt = 0; nt < 4; nt++) {
                    int c = warp_n + nt * 8 + (lane & 3) * 2;
                    *(float2*)&sM[rl * 132 + c] =
                        make_float2(acc[mt][nt][0], acc[mt][nt][1]);
                    *(float2*)&sM[(rl + 8) * 132 + c] =
                        make_float2(acc[mt][nt][2], acc[mt][nt][3]);
                }
            }
        }
        __syncthreads();

        // contract: for each (batch-in-half, o<63): sum over 2 joints
        #pragma unroll
        for (int it = 0; it < 16; it++) {
            int idx = it * 256 + tid;            // 0..4095
            int bl = idx >> 6, o = idx & 63;
            if (o < 63) {
                int k = (o * 21846) >> 16;       // o/3
                int c = o - k * 3;
                int bglob = h * 64 + bl;
                const float* m = &sM[bl * 132 + k * 3];
                float4 a0 = *(const float4*)&sA2[bglob * 24 + c * 4];
                float4 a1 = *(const float4*)&sA2[bglob * 24 + 12 + c * 4];
                float acc2;
                acc2 = a0.x * m[0];
                acc2 = fmaf(a0.y, m[1], acc2);
                acc2 = fmaf(a0.z, m[2], acc2);
                acc2 = fmaf(a1.x, m[64], acc2);
                acc2 = fmaf(a1.y, m[65], acc2);
                acc2 = fmaf(a1.z, m[66], acc2);
                atomicAdd(&out[(size_t)(bm0 + bglob) * 63 + o], acc2);
            }
        }
        __syncthreads();
    }
}

// =====================================================================
extern "C" void kernel_launch(void* const* d_in, const int* in_sizes, int n_in,
                              void* d_out, int out_size)
{
    const float* beta  = (const float*)d_in[0];
    const float* theta = (const float*)d_in[1];
    const float* wrist = (const float*)d_in[2];
    const float* vt    = (const float*)d_in[3];
    const float* sd    = (const float*)d_in[4];
    const float* pd    = (const float*)d_in[5];
    const float* Jr    = (const float*)d_in[6];
    const float* hc    = (const float*)d_in[7];
    const float* hm    = (const float*)d_in[8];
    const float* wts   = (const float*)d_in[9];
    float* out = (float*)d_out;

    precomp_part<<<146 * NVS + 72, 384>>>(vt, sd, pd, Jr, wts);
    fk_kernel<<<1216, 256>>>(beta, theta, wrist, hc, hm, out);
    mma_fused<<<dim3(NP / 128, NB / 128), 256>>>(out);
}